// round 1
// baseline (speedup 1.0000x reference)
#include <cuda_runtime.h>
#include <math.h>
#include <stdint.h>

// ---------------------------------------------------------------------------
// Problem constants
//   B=16, T=3, N=2048, D=3, NUM_LATENTS=512, DIM=512, HIDDEN=48 (k=8)
//   BT = B*T = 48
// ---------------------------------------------------------------------------

// ------------------------- scratch (device globals) ------------------------
__device__ int   g_idx[16 * 512];
__device__ float g_emb_s[(size_t)48 * 512 * 512];     //  50 MB
__device__ float g_lnq [(size_t)48 * 512 * 512];      //  50 MB
__device__ float g_lnc [(size_t)48 * 2048 * 512];     // 201 MB
__device__ float g_q   [(size_t)48 * 512 * 512];      //  50 MB
__device__ float g_kv  [(size_t)48 * 2048 * 1024];    // 402 MB
__device__ float g_sc  [(size_t)48 * 512 * 2048];     // 201 MB
__device__ float g_att [(size_t)48 * 512 * 512];      //  50 MB
__device__ float g_x   [(size_t)48 * 512 * 512];      //  50 MB
__device__ float g_xn  [(size_t)48 * 512 * 512];      //  50 MB
__device__ float g_h   [(size_t)24576 * 4096];        // 402 MB
__device__ float g_ag  [(size_t)24576 * 2048];        // 201 MB

// ------------------------- block reductions --------------------------------
__device__ __forceinline__ float blockReduceSum(float v, float* red) {
    #pragma unroll
    for (int o = 16; o; o >>= 1) v += __shfl_down_sync(0xffffffffu, v, o);
    int lane = threadIdx.x & 31, w = threadIdx.x >> 5;
    if (lane == 0) red[w] = v;
    __syncthreads();
    if (threadIdx.x < 32) {
        float s = (threadIdx.x < (blockDim.x >> 5)) ? red[threadIdx.x] : 0.0f;
        #pragma unroll
        for (int o = 16; o; o >>= 1) s += __shfl_down_sync(0xffffffffu, s, o);
        if (threadIdx.x == 0) red[0] = s;
    }
    __syncthreads();
    float r = red[0];
    __syncthreads();
    return r;
}

__device__ __forceinline__ float blockReduceMax(float v, float* red) {
    #pragma unroll
    for (int o = 16; o; o >>= 1) v = fmaxf(v, __shfl_down_sync(0xffffffffu, v, o));
    int lane = threadIdx.x & 31, w = threadIdx.x >> 5;
    if (lane == 0) red[w] = v;
    __syncthreads();
    if (threadIdx.x < 32) {
        float s = (threadIdx.x < (blockDim.x >> 5)) ? red[threadIdx.x] : -3.0e38f;
        #pragma unroll
        for (int o = 16; o; o >>= 1) s = fmaxf(s, __shfl_down_sync(0xffffffffu, s, o));
        if (threadIdx.x == 0) red[0] = s;
    }
    __syncthreads();
    float r = red[0];
    __syncthreads();
    return r;
}

// ------------------------- FPS (farthest point sampling) -------------------
// One block per batch (16 blocks), 1024 threads, 2 points/thread.
// Matches jnp semantics: dists init 1e10, last=0; per step:
//   d = sum((pts - pts[last])^2)   (no FMA contraction, (xx+yy)+zz order)
//   dists = min(dists, d); nxt = argmax(dists) (first index wins ties)
__global__ void fps_kernel(const float* __restrict__ pc, int* __restrict__ idx) {
    int b = blockIdx.x;
    int t = threadIdx.x;
    const float* pts = pc + (size_t)b * 3 * 2048 * 3;   // pc[b, 0, :, :]
    int t1 = t + 1024;
    float x0 = pts[t * 3 + 0], y0 = pts[t * 3 + 1], z0 = pts[t * 3 + 2];
    float x1 = pts[t1 * 3 + 0], y1 = pts[t1 * 3 + 1], z1 = pts[t1 * 3 + 2];
    float d0 = 1e10f, d1 = 1e10f;

    __shared__ float lx, ly, lz;
    __shared__ float sv[32];
    __shared__ int   si[32];
    if (t == 0) { lx = pts[0]; ly = pts[1]; lz = pts[2]; idx[b * 512] = 0; }
    __syncthreads();

    for (int s = 1; s < 512; s++) {
        float ax = __fadd_rn(x0, -lx), ay = __fadd_rn(y0, -ly), az = __fadd_rn(z0, -lz);
        float e0 = __fadd_rn(__fadd_rn(__fmul_rn(ax, ax), __fmul_rn(ay, ay)), __fmul_rn(az, az));
        float bx = __fadd_rn(x1, -lx), by = __fadd_rn(y1, -ly), bz = __fadd_rn(z1, -lz);
        float e1 = __fadd_rn(__fadd_rn(__fmul_rn(bx, bx), __fmul_rn(by, by)), __fmul_rn(bz, bz));
        d0 = fminf(d0, e0);
        d1 = fminf(d1, e1);

        float v;
        int   vi;
        if (d1 > d0) { v = d1; vi = t1; } else { v = d0; vi = t; }
        #pragma unroll
        for (int o = 16; o; o >>= 1) {
            float ov = __shfl_down_sync(0xffffffffu, v, o);
            int   oi = __shfl_down_sync(0xffffffffu, vi, o);
            if (ov > v || (ov == v && oi < vi)) { v = ov; vi = oi; }
        }
        int lane = t & 31, w = t >> 5;
        if (lane == 0) { sv[w] = v; si[w] = vi; }
        __syncthreads();
        if (t < 32) {
            v = sv[t]; vi = si[t];
            #pragma unroll
            for (int o = 16; o; o >>= 1) {
                float ov = __shfl_down_sync(0xffffffffu, v, o);
                int   oi = __shfl_down_sync(0xffffffffu, vi, o);
                if (ov > v || (ov == v && oi < vi)) { v = ov; vi = oi; }
            }
            if (t == 0) {
                idx[b * 512 + s] = vi;
                lx = pts[vi * 3 + 0]; ly = pts[vi * 3 + 1]; lz = pts[vi * 3 + 2];
            }
        }
        __syncthreads();
    }
}

// ------------------------- fused point-embed + LayerNorm -------------------
// Block = 512 threads, one thread per output channel j (j<256: pc-half,
// j>=256: pc2-half). Each thread keeps its pe_w column (51 floats) in regs.
// 8 points per block; feats in SMEM; block-wide LN over all 512 channels.
template <bool GATHER>
__global__ void embed_ln_kernel(const float* __restrict__ pc, const float* __restrict__ pc2,
                                const float* __restrict__ basis,
                                const float* __restrict__ pe_w, const float* __restrict__ pe_b,
                                const float* __restrict__ lng, const float* __restrict__ lnb,
                                const int* __restrict__ idx,
                                float* __restrict__ emb_out, float* __restrict__ ln_out) {
    const int j = threadIdx.x;          // 0..511
    const int half = j >> 8;
    const int col  = j & 255;
    float w[51];
    #pragma unroll
    for (int i = 0; i < 51; i++) w[i] = pe_w[i * 256 + col];
    const float pb = pe_b[col];
    const float gj = lng[j], bj = lnb[j];

    __shared__ float sx[2][3];
    __shared__ float sf[2][51];
    __shared__ float red[32];

    for (int p = 0; p < 8; p++) {
        long row = (long)blockIdx.x * 8 + p;
        long bt, n;
        if (GATHER) {
            bt = row >> 9;
            int m = (int)(row & 511);
            int b = (int)(bt / 3);
            n = idx[b * 512 + m];
        } else {
            bt = row >> 11;
            n = row & 2047;
        }
        size_t base = ((size_t)bt * 2048 + (size_t)n) * 3;
        if (j < 3)           sx[0][j]     = pc[base + j];
        else if (j < 6)      sx[1][j - 3] = pc2[base + j - 3];
        __syncthreads();

        if (j < 24) {
            float pr = sx[0][0] * basis[j] + sx[0][1] * basis[24 + j] + sx[0][2] * basis[48 + j];
            sf[0][j] = sinf(pr);
            sf[0][24 + j] = cosf(pr);
        } else if (j >= 32 && j < 56) {
            int e = j - 32;
            float pr = sx[1][0] * basis[e] + sx[1][1] * basis[24 + e] + sx[1][2] * basis[48 + e];
            sf[1][e] = sinf(pr);
            sf[1][24 + e] = cosf(pr);
        } else if (j >= 64 && j < 67) {
            sf[0][48 + (j - 64)] = sx[0][j - 64];
        } else if (j >= 67 && j < 70) {
            sf[1][48 + (j - 67)] = sx[1][j - 67];
        }
        __syncthreads();

        float acc = pb;
        #pragma unroll
        for (int i = 0; i < 51; i++) acc += w[i] * sf[half][i];

        float mean = blockReduceSum(acc, red) * (1.0f / 512.0f);
        float d = acc - mean;
        float var = blockReduceSum(d * d, red) * (1.0f / 512.0f);
        float ln = d * rsqrtf(var + 1e-5f) * gj + bj;

        size_t o = (size_t)row * 512 + j;
        if (GATHER) emb_out[o] = acc;
        ln_out[o] = ln;
        __syncthreads();
    }
}

// ------------------------- generic SGEMM 128x128x8 -------------------------
// C[M,N] = A[M,K] @ op(B) ;  TRANSB: B stored [N,K] row-major (dot of rows).
// EPI: 0 none, 1 +bias[n], 2 +bias[n] + res[m,n] (res has ldc).
template <int EPI, bool TRANSB>
__global__ void sgemm(const float* __restrict__ A, const float* __restrict__ B,
                      float* __restrict__ C, int M, int N, int K,
                      int lda, int ldb, int ldc,
                      size_t sA, size_t sB, size_t sC,
                      const float* __restrict__ bias, const float* __restrict__ res) {
    __shared__ float As[8][128];
    __shared__ float Bs[8][128];
    const int t = threadIdx.x;
    const int bm = blockIdx.y * 128, bn = blockIdx.x * 128;
    A += (size_t)blockIdx.z * sA;
    B += (size_t)blockIdx.z * sB;
    C += (size_t)blockIdx.z * sC;
    const float* resp = res;
    if (EPI == 2) resp = res + (size_t)blockIdx.z * sC;

    const int tx = t & 15, ty = t >> 4;
    float acc[8][8];
    #pragma unroll
    for (int i = 0; i < 8; i++)
        #pragma unroll
        for (int jj = 0; jj < 8; jj++) acc[i][jj] = 0.0f;

    const int arow = t >> 1, ak = (t & 1) * 4;
    int brow, bcol;
    if (TRANSB) { brow = t >> 1; bcol = (t & 1) * 4; }   // brow = n, bcol = k
    else        { brow = t >> 5; bcol = (t & 31) * 4; }  // brow = k, bcol = n

    for (int k0 = 0; k0 < K; k0 += 8) {
        float4 av = *(const float4*)(A + (size_t)(bm + arow) * lda + k0 + ak);
        As[ak + 0][arow] = av.x;
        As[ak + 1][arow] = av.y;
        As[ak + 2][arow] = av.z;
        As[ak + 3][arow] = av.w;
        if (TRANSB) {
            float4 bv = *(const float4*)(B + (size_t)(bn + brow) * ldb + k0 + bcol);
            Bs[bcol + 0][brow] = bv.x;
            Bs[bcol + 1][brow] = bv.y;
            Bs[bcol + 2][brow] = bv.z;
            Bs[bcol + 3][brow] = bv.w;
        } else {
            float4 bv = *(const float4*)(B + (size_t)(k0 + brow) * ldb + bn + bcol);
            *(float4*)&Bs[brow][bcol] = bv;
        }
        __syncthreads();
        #pragma unroll
        for (int k = 0; k < 8; k++) {
            float a[8], bb[8];
            *(float4*)&a[0]  = *(const float4*)&As[k][ty * 8];
            *(float4*)&a[4]  = *(const float4*)&As[k][ty * 8 + 4];
            *(float4*)&bb[0] = *(const float4*)&Bs[k][tx * 8];
            *(float4*)&bb[4] = *(const float4*)&Bs[k][tx * 8 + 4];
            #pragma unroll
            for (int i = 0; i < 8; i++)
                #pragma unroll
                for (int jj = 0; jj < 8; jj++)
                    acc[i][jj] = fmaf(a[i], bb[jj], acc[i][jj]);
        }
        __syncthreads();
    }

    #pragma unroll
    for (int i = 0; i < 8; i++) {
        size_t r = (size_t)(bm + ty * 8 + i);
        #pragma unroll
        for (int jj = 0; jj < 8; jj += 4) {
            size_t c = (size_t)(bn + tx * 8 + jj);
            float4 v;
            v.x = acc[i][jj]; v.y = acc[i][jj + 1]; v.z = acc[i][jj + 2]; v.w = acc[i][jj + 3];
            if (EPI >= 1) {
                v.x += bias[c]; v.y += bias[c + 1]; v.z += bias[c + 2]; v.w += bias[c + 3];
            }
            if (EPI == 2) {
                float4 rv = *(const float4*)(resp + r * (size_t)ldc + c);
                v.x += rv.x; v.y += rv.y; v.z += rv.z; v.w += rv.w;
            }
            *(float4*)(C + r * (size_t)ldc + c) = v;
        }
    }
}

// ------------------------- softmax (rows of 2048) ---------------------------
__global__ void softmax_kernel(float* __restrict__ s) {
    const size_t row = blockIdx.x;
    float* p = s + row * 2048;
    const int t = threadIdx.x;             // 256 threads
    const float scale = 0.044194173824159216f;  // 512^-0.5
    __shared__ float red[32];
    float v[8];
    float mx = -3.0e38f;
    #pragma unroll
    for (int i = 0; i < 8; i++) {
        v[i] = p[t + i * 256] * scale;
        mx = fmaxf(mx, v[i]);
    }
    mx = blockReduceMax(mx, red);
    float sum = 0.0f;
    #pragma unroll
    for (int i = 0; i < 8; i++) {
        v[i] = expf(v[i] - mx);
        sum += v[i];
    }
    sum = blockReduceSum(sum, red);
    float inv = 1.0f / sum;
    #pragma unroll
    for (int i = 0; i < 8; i++) p[t + i * 256] = v[i] * inv;
}

// ------------------------- LayerNorm (dim 512) ------------------------------
__global__ void ln_kernel(const float* __restrict__ x, float* __restrict__ y,
                          const float* __restrict__ g, const float* __restrict__ b) {
    const size_t row = blockIdx.x;
    const int j = threadIdx.x;  // 512
    __shared__ float red[32];
    float v = x[row * 512 + j];
    float mean = blockReduceSum(v, red) * (1.0f / 512.0f);
    float d = v - mean;
    float var = blockReduceSum(d * d, red) * (1.0f / 512.0f);
    y[row * 512 + j] = d * rsqrtf(var + 1e-5f) * g[j] + b[j];
}

// ------------------------- a * gelu(g) (exact) ------------------------------
__global__ void geluprod_kernel(const float* __restrict__ h, float* __restrict__ ag) {
    size_t i = (size_t)blockIdx.x * blockDim.x + threadIdx.x;
    size_t m = i >> 11, j = i & 2047;
    float a = h[m * 4096 + j];
    float gg = h[m * 4096 + 2048 + j];
    float ge = 0.5f * gg * (1.0f + erff(gg * 0.7071067811865475f));
    ag[i] = a * ge;
}

// ---------------------------------------------------------------------------
extern "C" void kernel_launch(void* const* d_in, const int* in_sizes, int n_in,
                              void* d_out, int out_size) {
    const float* pc    = (const float*)d_in[0];
    const float* pc2   = (const float*)d_in[1];
    const float* basis = (const float*)d_in[2];
    const float* pe_w  = (const float*)d_in[3];
    const float* pe_b  = (const float*)d_in[4];
    const float* lnq_g = (const float*)d_in[5];
    const float* lnq_b = (const float*)d_in[6];
    const float* lnc_g = (const float*)d_in[7];
    const float* lnc_b = (const float*)d_in[8];
    const float* wq    = (const float*)d_in[9];
    const float* wkv   = (const float*)d_in[10];
    const float* wo    = (const float*)d_in[11];
    const float* bo    = (const float*)d_in[12];
    const float* lnf_g = (const float*)d_in[13];
    const float* lnf_b = (const float*)d_in[14];
    const float* w1    = (const float*)d_in[15];
    const float* b1    = (const float*)d_in[16];
    const float* w2    = (const float*)d_in[17];
    const float* b2    = (const float*)d_in[18];
    float* out = (float*)d_out;

    void *vp;
    int*   p_idx;  cudaGetSymbolAddress(&vp, g_idx);   p_idx  = (int*)vp;
    float* p_embs; cudaGetSymbolAddress(&vp, g_emb_s); p_embs = (float*)vp;
    float* p_lnq;  cudaGetSymbolAddress(&vp, g_lnq);   p_lnq  = (float*)vp;
    float* p_lnc;  cudaGetSymbolAddress(&vp, g_lnc);   p_lnc  = (float*)vp;
    float* p_q;    cudaGetSymbolAddress(&vp, g_q);     p_q    = (float*)vp;
    float* p_kv;   cudaGetSymbolAddress(&vp, g_kv);    p_kv   = (float*)vp;
    float* p_sc;   cudaGetSymbolAddress(&vp, g_sc);    p_sc   = (float*)vp;
    float* p_att;  cudaGetSymbolAddress(&vp, g_att);   p_att  = (float*)vp;
    float* p_x;    cudaGetSymbolAddress(&vp, g_x);     p_x    = (float*)vp;
    float* p_xn;   cudaGetSymbolAddress(&vp, g_xn);    p_xn   = (float*)vp;
    float* p_h;    cudaGetSymbolAddress(&vp, g_h);     p_h    = (float*)vp;
    float* p_ag;   cudaGetSymbolAddress(&vp, g_ag);    p_ag   = (float*)vp;

    // 1) FPS indices (16 independent batches)
    fps_kernel<<<16, 1024>>>(pc, p_idx);

    // 2) fused embed + LN for sampled (keeps emb_s for residual) and context
    embed_ln_kernel<true ><<<48 * 512 / 8, 512>>>(pc, pc2, basis, pe_w, pe_b,
                                                  lnq_g, lnq_b, p_idx, p_embs, p_lnq);
    embed_ln_kernel<false><<<48 * 2048 / 8, 512>>>(pc, pc2, basis, pe_w, pe_b,
                                                   lnc_g, lnc_b, nullptr, nullptr, p_lnc);

    // 3) q = lnq @ wq                        (24576,512)x(512,512)
    sgemm<0, false><<<dim3(512 / 128, 24576 / 128, 1), 256>>>(
        p_lnq, wq, p_q, 24576, 512, 512, 512, 512, 512, 0, 0, 0, nullptr, nullptr);

    // 4) kv = lnc @ wkv                      (98304,512)x(512,1024)
    sgemm<0, false><<<dim3(1024 / 128, 98304 / 128, 1), 256>>>(
        p_lnc, wkv, p_kv, 98304, 1024, 512, 512, 1024, 1024, 0, 0, 0, nullptr, nullptr);

    // 5) scores[b] = q[b] @ k[b]^T           batched 48, NT
    sgemm<0, true><<<dim3(2048 / 128, 512 / 128, 48), 256>>>(
        p_q, p_kv, p_sc, 512, 2048, 512, 512, 1024, 2048,
        (size_t)512 * 512, (size_t)2048 * 1024, (size_t)512 * 2048, nullptr, nullptr);

    // 6) softmax(scores * scale)
    softmax_kernel<<<24576, 256>>>(p_sc);

    // 7) attn_out[b] = attn[b] @ v[b]        batched 48, NN (v = kv cols 512:1024)
    sgemm<0, false><<<dim3(512 / 128, 512 / 128, 48), 256>>>(
        p_sc, p_kv + 512, p_att, 512, 512, 2048, 2048, 1024, 512,
        (size_t)512 * 2048, (size_t)2048 * 1024, (size_t)512 * 512, nullptr, nullptr);

    // 8) x = attn_out @ wo + bo + emb_s
    sgemm<2, false><<<dim3(512 / 128, 24576 / 128, 1), 256>>>(
        p_att, wo, p_x, 24576, 512, 512, 512, 512, 512, 0, 0, 0, bo, p_embs);

    // 9) xn = LN(x)
    ln_kernel<<<24576, 512>>>(p_x, p_xn, lnf_g, lnf_b);

    // 10) h = xn @ w1 + b1                   (24576,512)x(512,4096)
    sgemm<1, false><<<dim3(4096 / 128, 24576 / 128, 1), 256>>>(
        p_xn, w1, p_h, 24576, 4096, 512, 512, 4096, 4096, 0, 0, 0, b1, nullptr);

    // 11) ag = a * gelu(g)
    geluprod_kernel<<<(24576 * 2048) / 256, 256>>>(p_h, p_ag);

    // 12) out = ag @ w2 + b2 + x             (24576,2048)x(2048,512)
    sgemm<2, false><<<dim3(512 / 128, 24576 / 128, 1), 256>>>(
        p_ag, w2, out, 24576, 512, 2048, 2048, 512, 512, 0, 0, 0, b2, p_x);
}

// round 2
// speedup vs baseline: 2.5490x; 2.5490x over previous
#include <cuda_runtime.h>
#include <math.h>
#include <stdint.h>

// ---------------------------------------------------------------------------
// B=16, T=3, N=2048, D=3, NUM_LATENTS=512, DIM=512, HIDDEN=48 (k=8), BT=48
// ---------------------------------------------------------------------------

// ------------------------- scratch (device globals) ------------------------
__device__ int   g_idx[16 * 512];
__device__ float g_emb_s[(size_t)48 * 512 * 512];
__device__ float g_lnq [(size_t)48 * 512 * 512];
__device__ float g_lnc [(size_t)48 * 2048 * 512];
__device__ float g_q   [(size_t)48 * 512 * 512];
__device__ float g_kv  [(size_t)48 * 2048 * 1024];
__device__ float g_sc  [(size_t)48 * 512 * 2048];
__device__ float g_att [(size_t)48 * 512 * 512];
__device__ float g_x   [(size_t)48 * 512 * 512];
__device__ float g_xn  [(size_t)48 * 512 * 512];
__device__ float g_h   [(size_t)24576 * 4096];
__device__ float g_ag  [(size_t)24576 * 2048];
__device__ float g_wc  [4194304];   // tf32-rounded weights: wq|wkv|wo|w1|w2

// ------------------------- helpers -----------------------------------------
__device__ __forceinline__ float tf32r(float x) {
    unsigned u;
    asm("cvt.rna.tf32.f32 %0, %1;" : "=r"(u) : "f"(x));
    return __uint_as_float(u);
}

__device__ __forceinline__ void cp16(float* dst, const float* src) {
    unsigned d = (unsigned)__cvta_generic_to_shared(dst);
    asm volatile("cp.async.cg.shared.global [%0], [%1], 16;" :: "r"(d), "l"(src));
}

__device__ __forceinline__ void mma8(float* d, const unsigned* a, const unsigned* b) {
    asm volatile(
        "mma.sync.aligned.m16n8k8.row.col.f32.tf32.tf32.f32 "
        "{%0,%1,%2,%3}, {%4,%5,%6,%7}, {%8,%9}, {%0,%1,%2,%3};"
        : "+f"(d[0]), "+f"(d[1]), "+f"(d[2]), "+f"(d[3])
        : "r"(a[0]), "r"(a[1]), "r"(a[2]), "r"(a[3]), "r"(b[0]), "r"(b[1]));
}

__device__ __forceinline__ float blockReduceSum(float v, float* red) {
    #pragma unroll
    for (int o = 16; o; o >>= 1) v += __shfl_down_sync(0xffffffffu, v, o);
    int lane = threadIdx.x & 31, w = threadIdx.x >> 5;
    if (lane == 0) red[w] = v;
    __syncthreads();
    if (threadIdx.x < 32) {
        float s = (threadIdx.x < (blockDim.x >> 5)) ? red[threadIdx.x] : 0.0f;
        #pragma unroll
        for (int o = 16; o; o >>= 1) s += __shfl_down_sync(0xffffffffu, s, o);
        if (threadIdx.x == 0) red[0] = s;
    }
    __syncthreads();
    float r = red[0];
    __syncthreads();
    return r;
}

__device__ __forceinline__ float blockReduceMax(float v, float* red) {
    #pragma unroll
    for (int o = 16; o; o >>= 1) v = fmaxf(v, __shfl_down_sync(0xffffffffu, v, o));
    int lane = threadIdx.x & 31, w = threadIdx.x >> 5;
    if (lane == 0) red[w] = v;
    __syncthreads();
    if (threadIdx.x < 32) {
        float s = (threadIdx.x < (blockDim.x >> 5)) ? red[threadIdx.x] : -3.0e38f;
        #pragma unroll
        for (int o = 16; o; o >>= 1) s = fmaxf(s, __shfl_down_sync(0xffffffffu, s, o));
        if (threadIdx.x == 0) red[0] = s;
    }
    __syncthreads();
    float r = red[0];
    __syncthreads();
    return r;
}

// ------------------------- FPS ---------------------------------------------
__global__ void fps_kernel(const float* __restrict__ pc, int* __restrict__ idx) {
    int b = blockIdx.x;
    int t = threadIdx.x;
    const float* pts = pc + (size_t)b * 3 * 2048 * 3;
    int t1 = t + 1024;
    float x0 = pts[t * 3 + 0], y0 = pts[t * 3 + 1], z0 = pts[t * 3 + 2];
    float x1 = pts[t1 * 3 + 0], y1 = pts[t1 * 3 + 1], z1 = pts[t1 * 3 + 2];
    float d0 = 1e10f, d1 = 1e10f;

    __shared__ float lx, ly, lz;
    __shared__ float sv[32];
    __shared__ int   si[32];
    if (t == 0) { lx = pts[0]; ly = pts[1]; lz = pts[2]; idx[b * 512] = 0; }
    __syncthreads();

    for (int s = 1; s < 512; s++) {
        float ax = __fadd_rn(x0, -lx), ay = __fadd_rn(y0, -ly), az = __fadd_rn(z0, -lz);
        float e0 = __fadd_rn(__fadd_rn(__fmul_rn(ax, ax), __fmul_rn(ay, ay)), __fmul_rn(az, az));
        float bx = __fadd_rn(x1, -lx), by = __fadd_rn(y1, -ly), bz = __fadd_rn(z1, -lz);
        float e1 = __fadd_rn(__fadd_rn(__fmul_rn(bx, bx), __fmul_rn(by, by)), __fmul_rn(bz, bz));
        d0 = fminf(d0, e0);
        d1 = fminf(d1, e1);

        float v;
        int   vi;
        if (d1 > d0) { v = d1; vi = t1; } else { v = d0; vi = t; }
        #pragma unroll
        for (int o = 16; o; o >>= 1) {
            float ov = __shfl_down_sync(0xffffffffu, v, o);
            int   oi = __shfl_down_sync(0xffffffffu, vi, o);
            if (ov > v || (ov == v && oi < vi)) { v = ov; vi = oi; }
        }
        int lane = t & 31, w = t >> 5;
        if (lane == 0) { sv[w] = v; si[w] = vi; }
        __syncthreads();
        if (t < 32) {
            v = sv[t]; vi = si[t];
            #pragma unroll
            for (int o = 16; o; o >>= 1) {
                float ov = __shfl_down_sync(0xffffffffu, v, o);
                int   oi = __shfl_down_sync(0xffffffffu, vi, o);
                if (ov > v || (ov == v && oi < vi)) { v = ov; vi = oi; }
            }
            if (t == 0) {
                idx[b * 512 + s] = vi;
                lx = pts[vi * 3 + 0]; ly = pts[vi * 3 + 1]; lz = pts[vi * 3 + 2];
            }
        }
        __syncthreads();
    }
}

// ------------------------- fused point-embed + LayerNorm --------------------
// ln_out is tf32-rounded (feeds GEMM A side); emb_out stays full fp32.
template <bool GATHER>
__global__ void embed_ln_kernel(const float* __restrict__ pc, const float* __restrict__ pc2,
                                const float* __restrict__ basis,
                                const float* __restrict__ pe_w, const float* __restrict__ pe_b,
                                const float* __restrict__ lng, const float* __restrict__ lnb,
                                const int* __restrict__ idx,
                                float* __restrict__ emb_out, float* __restrict__ ln_out) {
    const int j = threadIdx.x;
    const int half = j >> 8;
    const int col  = j & 255;
    float w[51];
    #pragma unroll
    for (int i = 0; i < 51; i++) w[i] = pe_w[i * 256 + col];
    const float pb = pe_b[col];
    const float gj = lng[j], bj = lnb[j];

    __shared__ float sx[2][3];
    __shared__ float sf[2][51];
    __shared__ float red[32];

    for (int p = 0; p < 8; p++) {
        long row = (long)blockIdx.x * 8 + p;
        long bt, n;
        if (GATHER) {
            bt = row >> 9;
            int m = (int)(row & 511);
            int b = (int)(bt / 3);
            n = idx[b * 512 + m];
        } else {
            bt = row >> 11;
            n = row & 2047;
        }
        size_t base = ((size_t)bt * 2048 + (size_t)n) * 3;
        if (j < 3)           sx[0][j]     = pc[base + j];
        else if (j < 6)      sx[1][j - 3] = pc2[base + j - 3];
        __syncthreads();

        if (j < 24) {
            float pr = sx[0][0] * basis[j] + sx[0][1] * basis[24 + j] + sx[0][2] * basis[48 + j];
            sf[0][j] = sinf(pr);
            sf[0][24 + j] = cosf(pr);
        } else if (j >= 32 && j < 56) {
            int e = j - 32;
            float pr = sx[1][0] * basis[e] + sx[1][1] * basis[24 + e] + sx[1][2] * basis[48 + e];
            sf[1][e] = sinf(pr);
            sf[1][24 + e] = cosf(pr);
        } else if (j >= 64 && j < 67) {
            sf[0][48 + (j - 64)] = sx[0][j - 64];
        } else if (j >= 67 && j < 70) {
            sf[1][48 + (j - 67)] = sx[1][j - 67];
        }
        __syncthreads();

        float acc = pb;
        #pragma unroll
        for (int i = 0; i < 51; i++) acc += w[i] * sf[half][i];

        float mean = blockReduceSum(acc, red) * (1.0f / 512.0f);
        float d = acc - mean;
        float var = blockReduceSum(d * d, red) * (1.0f / 512.0f);
        float ln = d * rsqrtf(var + 1e-5f) * gj + bj;

        size_t o = (size_t)row * 512 + j;
        if (GATHER) emb_out[o] = acc;
        ln_out[o] = tf32r(ln);
        __syncthreads();
    }
}

// ------------------------- TF32 tensor-core GEMM ----------------------------
// C[M,N] = A[M,K] @ op(B). TRANSB: B stored [N,K] row-major.
// BM=BN=128, BK=32, 256 threads, warp tile 64x32, mma m16n8k8 tf32.
// Inputs must already be tf32-rounded fp32. EPI: 0 none, 1 +bias, 2 +bias+res.
// CVT: round output to tf32 (when it feeds another GEMM).
#define SM_BUF 4608   // floats per buffer per matrix (128*36)

template <int EPI, bool TRANSB, bool CVT>
__global__ void __launch_bounds__(256, 2)
tgemm(const float* __restrict__ A, const float* __restrict__ B, float* __restrict__ C,
      int K, int lda, int ldb, int ldc,
      size_t sA, size_t sB, size_t sC,
      const float* __restrict__ bias, const float* __restrict__ res) {
    extern __shared__ float sm[];
    float* As = sm;                 // 2 * SM_BUF
    float* Bs = sm + 2 * SM_BUF;    // 2 * SM_BUF

    const int t = threadIdx.x;
    const int bm = blockIdx.y * 128, bn = blockIdx.x * 128;
    A += (size_t)blockIdx.z * sA;
    B += (size_t)blockIdx.z * sB;
    C += (size_t)blockIdx.z * sC;
    const float* resp = (EPI == 2) ? res + (size_t)blockIdx.z * sC : nullptr;

    const int lane = t & 31, wid = t >> 5;
    const int wm = (wid >> 2) * 64, wn = (wid & 3) * 32;
    const int gq = lane >> 2, tq = lane & 3;

    float acc[4][4][4];
    #pragma unroll
    for (int mi = 0; mi < 4; mi++)
        #pragma unroll
        for (int ni = 0; ni < 4; ni++)
            #pragma unroll
            for (int r = 0; r < 4; r++) acc[mi][ni][r] = 0.0f;

    const int T = K >> 5;

    // ---- async tile loader ----
    auto issue = [&](int kt, int buf) {
        const float* Ag = A + (size_t)bm * lda + kt * 32;
        float* Ab = As + buf * SM_BUF;
        #pragma unroll
        for (int i = 0; i < 4; i++) {
            int c = t + 256 * i;
            int row = c >> 3, kc = (c & 7) * 4;
            cp16(Ab + row * 36 + kc, Ag + (size_t)row * lda + kc);
        }
        float* Bb = Bs + buf * SM_BUF;
        if (TRANSB) {
            const float* Bg = B + (size_t)bn * ldb + kt * 32;
            #pragma unroll
            for (int i = 0; i < 4; i++) {
                int c = t + 256 * i;
                int row = c >> 3, kc = (c & 7) * 4;
                cp16(Bb + row * 36 + kc, Bg + (size_t)row * ldb + kc);
            }
        } else {
            const float* Bg = B + (size_t)(kt * 32) * ldb + bn;
            #pragma unroll
            for (int i = 0; i < 4; i++) {
                int c = t + 256 * i;
                int row = c >> 5, nc = (c & 31) * 4;
                cp16(Bb + row * 136 + nc, Bg + (size_t)row * ldb + nc);
            }
        }
        asm volatile("cp.async.commit_group;");
    };

    issue(0, 0);
    for (int kt = 0; kt < T; kt++) {
        if (kt + 1 < T) {
            issue(kt + 1, (kt + 1) & 1);
            asm volatile("cp.async.wait_group 1;");
        } else {
            asm volatile("cp.async.wait_group 0;");
        }
        __syncthreads();

        const float* Ab = As + (kt & 1) * SM_BUF;
        const float* Bb = Bs + (kt & 1) * SM_BUF;

        #pragma unroll
        for (int ki = 0; ki < 4; ki++) {
            unsigned a[4][4], b[4][2];
            #pragma unroll
            for (int mi = 0; mi < 4; mi++) {
                const float* p = Ab + (size_t)(wm + mi * 16 + gq) * 36 + ki * 8 + tq;
                a[mi][0] = __float_as_uint(p[0]);
                a[mi][1] = __float_as_uint(p[8 * 36]);
                a[mi][2] = __float_as_uint(p[4]);
                a[mi][3] = __float_as_uint(p[8 * 36 + 4]);
            }
            #pragma unroll
            for (int ni = 0; ni < 4; ni++) {
                if (TRANSB) {
                    const float* p = Bb + (size_t)(wn + ni * 8 + gq) * 36 + ki * 8 + tq;
                    b[ni][0] = __float_as_uint(p[0]);
                    b[ni][1] = __float_as_uint(p[4]);
                } else {
                    const float* p = Bb + (size_t)(ki * 8 + tq) * 136 + wn + ni * 8 + gq;
                    b[ni][0] = __float_as_uint(p[0]);
                    b[ni][1] = __float_as_uint(p[4 * 136]);
                }
            }
            #pragma unroll
            for (int mi = 0; mi < 4; mi++)
                #pragma unroll
                for (int ni = 0; ni < 4; ni++)
                    mma8(acc[mi][ni], a[mi], b[ni]);
        }
        __syncthreads();
    }

    // ---- epilogue ----
    #pragma unroll
    for (int mi = 0; mi < 4; mi++) {
        size_t r0 = (size_t)(bm + wm + mi * 16 + gq);
        #pragma unroll
        for (int ni = 0; ni < 4; ni++) {
            size_t c0 = (size_t)(bn + wn + ni * 8 + tq * 2);
            float2 v0 = make_float2(acc[mi][ni][0], acc[mi][ni][1]);
            float2 v1 = make_float2(acc[mi][ni][2], acc[mi][ni][3]);
            if (EPI >= 1) {
                float b0 = bias[c0], b1 = bias[c0 + 1];
                v0.x += b0; v0.y += b1; v1.x += b0; v1.y += b1;
            }
            if (EPI == 2) {
                float2 r0v = *(const float2*)(resp + r0 * ldc + c0);
                float2 r1v = *(const float2*)(resp + (r0 + 8) * ldc + c0);
                v0.x += r0v.x; v0.y += r0v.y; v1.x += r1v.x; v1.y += r1v.y;
            }
            if (CVT) {
                v0.x = tf32r(v0.x); v0.y = tf32r(v0.y);
                v1.x = tf32r(v1.x); v1.y = tf32r(v1.y);
            }
            *(float2*)(C + r0 * ldc + c0) = v0;
            *(float2*)(C + (r0 + 8) * ldc + c0) = v1;
        }
    }
}

// ------------------------- softmax (rows of 2048) ---------------------------
__global__ void softmax_kernel(float* __restrict__ s) {
    const size_t row = blockIdx.x;
    float* p = s + row * 2048;
    const int t = threadIdx.x;
    const float scale = 0.044194173824159216f;
    __shared__ float red[32];
    float v[8];
    float mx = -3.0e38f;
    #pragma unroll
    for (int i = 0; i < 8; i++) {
        v[i] = p[t + i * 256] * scale;
        mx = fmaxf(mx, v[i]);
    }
    mx = blockReduceMax(mx, red);
    float sum = 0.0f;
    #pragma unroll
    for (int i = 0; i < 8; i++) {
        v[i] = expf(v[i] - mx);
        sum += v[i];
    }
    sum = blockReduceSum(sum, red);
    float inv = 1.0f / sum;
    #pragma unroll
    for (int i = 0; i < 8; i++) p[t + i * 256] = tf32r(v[i] * inv);
}

// ------------------------- LayerNorm (dim 512), tf32 out --------------------
__global__ void ln_kernel(const float* __restrict__ x, float* __restrict__ y,
                          const float* __restrict__ g, const float* __restrict__ b) {
    const size_t row = blockIdx.x;
    const int j = threadIdx.x;
    __shared__ float red[32];
    float v = x[row * 512 + j];
    float mean = blockReduceSum(v, red) * (1.0f / 512.0f);
    float d = v - mean;
    float var = blockReduceSum(d * d, red) * (1.0f / 512.0f);
    y[row * 512 + j] = tf32r(d * rsqrtf(var + 1e-5f) * g[j] + b[j]);
}

// ------------------------- a * gelu(g), tf32 out -----------------------------
__global__ void geluprod_kernel(const float* __restrict__ h, float* __restrict__ ag) {
    size_t i = (size_t)blockIdx.x * blockDim.x + threadIdx.x;
    size_t m = i >> 11, j = i & 2047;
    float a = h[m * 4096 + j];
    float gg = h[m * 4096 + 2048 + j];
    float ge = 0.5f * gg * (1.0f + erff(gg * 0.7071067811865475f));
    ag[i] = tf32r(a * ge);
}

// ------------------------- weight tf32 round --------------------------------
__global__ void cvtw_kernel(const float* __restrict__ src, float* __restrict__ dst, int n) {
    int i = blockIdx.x * 256 + threadIdx.x;
    if (i < n) dst[i] = tf32r(src[i]);
}

// ---------------------------------------------------------------------------
extern "C" void kernel_launch(void* const* d_in, const int* in_sizes, int n_in,
                              void* d_out, int out_size) {
    const float* pc    = (const float*)d_in[0];
    const float* pc2   = (const float*)d_in[1];
    const float* basis = (const float*)d_in[2];
    const float* pe_w  = (const float*)d_in[3];
    const float* pe_b  = (const float*)d_in[4];
    const float* lnq_g = (const float*)d_in[5];
    const float* lnq_b = (const float*)d_in[6];
    const float* lnc_g = (const float*)d_in[7];
    const float* lnc_b = (const float*)d_in[8];
    const float* wq    = (const float*)d_in[9];
    const float* wkv   = (const float*)d_in[10];
    const float* wo    = (const float*)d_in[11];
    const float* bo    = (const float*)d_in[12];
    const float* lnf_g = (const float*)d_in[13];
    const float* lnf_b = (const float*)d_in[14];
    const float* w1    = (const float*)d_in[15];
    const float* b1    = (const float*)d_in[16];
    const float* w2    = (const float*)d_in[17];
    const float* b2    = (const float*)d_in[18];
    float* out = (float*)d_out;

    void *vp;
    int*   p_idx;  cudaGetSymbolAddress(&vp, g_idx);   p_idx  = (int*)vp;
    float* p_embs; cudaGetSymbolAddress(&vp, g_emb_s); p_embs = (float*)vp;
    float* p_lnq;  cudaGetSymbolAddress(&vp, g_lnq);   p_lnq  = (float*)vp;
    float* p_lnc;  cudaGetSymbolAddress(&vp, g_lnc);   p_lnc  = (float*)vp;
    float* p_q;    cudaGetSymbolAddress(&vp, g_q);     p_q    = (float*)vp;
    float* p_kv;   cudaGetSymbolAddress(&vp, g_kv);    p_kv   = (float*)vp;
    float* p_sc;   cudaGetSymbolAddress(&vp, g_sc);    p_sc   = (float*)vp;
    float* p_att;  cudaGetSymbolAddress(&vp, g_att);   p_att  = (float*)vp;
    float* p_x;    cudaGetSymbolAddress(&vp, g_x);     p_x    = (float*)vp;
    float* p_xn;   cudaGetSymbolAddress(&vp, g_xn);    p_xn   = (float*)vp;
    float* p_h;    cudaGetSymbolAddress(&vp, g_h);     p_h    = (float*)vp;
    float* p_ag;   cudaGetSymbolAddress(&vp, g_ag);    p_ag   = (float*)vp;
    float* p_wc;   cudaGetSymbolAddress(&vp, g_wc);    p_wc   = (float*)vp;

    float* wq_c  = p_wc;
    float* wkv_c = p_wc + 262144;
    float* wo_c  = p_wc + 786432;
    float* w1_c  = p_wc + 1048576;
    float* w2_c  = p_wc + 3145728;

    const int SMEM = 4 * SM_BUF * sizeof(float);   // 73728 B
    cudaFuncSetAttribute(tgemm<0, false, true >, cudaFuncAttributeMaxDynamicSharedMemorySize, SMEM);
    cudaFuncSetAttribute(tgemm<0, true,  false>, cudaFuncAttributeMaxDynamicSharedMemorySize, SMEM);
    cudaFuncSetAttribute(tgemm<1, false, false>, cudaFuncAttributeMaxDynamicSharedMemorySize, SMEM);
    cudaFuncSetAttribute(tgemm<2, false, false>, cudaFuncAttributeMaxDynamicSharedMemorySize, SMEM);

    // 0) weight conversion to tf32-rounded fp32
    cvtw_kernel<<<262144 / 256, 256>>>(wq,  wq_c,  262144);
    cvtw_kernel<<<524288 / 256, 256>>>(wkv, wkv_c, 524288);
    cvtw_kernel<<<262144 / 256, 256>>>(wo,  wo_c,  262144);
    cvtw_kernel<<<2097152 / 256, 256>>>(w1, w1_c,  2097152);
    cvtw_kernel<<<1048576 / 256, 256>>>(w2, w2_c,  1048576);

    // 1) FPS
    fps_kernel<<<16, 1024>>>(pc, p_idx);

    // 2) fused embed + LN (ln outputs tf32-rounded)
    embed_ln_kernel<true ><<<48 * 512 / 8, 512>>>(pc, pc2, basis, pe_w, pe_b,
                                                  lnq_g, lnq_b, p_idx, p_embs, p_lnq);
    embed_ln_kernel<false><<<48 * 2048 / 8, 512>>>(pc, pc2, basis, pe_w, pe_b,
                                                   lnc_g, lnc_b, nullptr, nullptr, p_lnc);

    // 3) q = lnq @ wq (out tf32)
    tgemm<0, false, true><<<dim3(4, 192, 1), 256, SMEM>>>(
        p_lnq, wq_c, p_q, 512, 512, 512, 512, 0, 0, 0, nullptr, nullptr);

    // 4) kv = lnc @ wkv (out tf32)
    tgemm<0, false, true><<<dim3(8, 768, 1), 256, SMEM>>>(
        p_lnc, wkv_c, p_kv, 512, 512, 1024, 1024, 0, 0, 0, nullptr, nullptr);

    // 5) scores[b] = q[b] @ k[b]^T (batched 48, NT)
    tgemm<0, true, false><<<dim3(16, 4, 48), 256, SMEM>>>(
        p_q, p_kv, p_sc, 512, 512, 1024, 2048,
        (size_t)512 * 512, (size_t)2048 * 1024, (size_t)512 * 2048, nullptr, nullptr);

    // 6) softmax (out tf32)
    softmax_kernel<<<24576, 256>>>(p_sc);

    // 7) attn_out[b] = attn[b] @ v[b] (out tf32)
    tgemm<0, false, true><<<dim3(4, 4, 48), 256, SMEM>>>(
        p_sc, p_kv + 512, p_att, 2048, 2048, 1024, 512,
        (size_t)512 * 2048, (size_t)2048 * 1024, (size_t)512 * 512, nullptr, nullptr);

    // 8) x = attn_out @ wo + bo + emb_s (fp32 out)
    tgemm<2, false, false><<<dim3(4, 192, 1), 256, SMEM>>>(
        p_att, wo_c, p_x, 512, 512, 512, 512, 0, 0, 0, bo, p_embs);

    // 9) xn = LN(x) (tf32 out)
    ln_kernel<<<24576, 512>>>(p_x, p_xn, lnf_g, lnf_b);

    // 10) h = xn @ w1 + b1
    tgemm<1, false, false><<<dim3(32, 192, 1), 256, SMEM>>>(
        p_xn, w1_c, p_h, 512, 512, 4096, 4096, 0, 0, 0, b1, nullptr);

    // 11) ag = a * gelu(g) (tf32 out)
    geluprod_kernel<<<(24576 * 2048) / 256, 256>>>(p_h, p_ag);

    // 12) out = ag @ w2 + b2 + x (fp32 out)
    tgemm<2, false, false><<<dim3(4, 192, 1), 256, SMEM>>>(
        p_ag, w2_c, out, 2048, 2048, 512, 512, 0, 0, 0, b2, p_x);
}

// round 4
// speedup vs baseline: 3.0044x; 1.1787x over previous
#include <cuda_runtime.h>
#include <cuda_fp16.h>
#include <math.h>
#include <stdint.h>

// ---------------------------------------------------------------------------
// B=16, T=3, N=2048, D=3, NUM_LATENTS=512, DIM=512, HIDDEN=48 (k=8), BT=48
// All GEMMs NT: C[M,N] = A[M,K] @ B[N,K]^T, fp16 inputs, fp32 accumulate,
// mma.sync.m16n8k16. Weights pre-transposed+converted once per launch.
// ---------------------------------------------------------------------------

// ------------------------- scratch (device globals) ------------------------
__device__ int    g_idx[16 * 512];
__device__ float  g_emb_s[(size_t)48 * 512 * 512];            // fp32 residual
__device__ __half g_lnq [(size_t)48 * 512 * 512];
__device__ __half g_lnc [(size_t)48 * 2048 * 512];
__device__ __half g_q   [(size_t)48 * 512 * 512];
__device__ __half g_k   [(size_t)48 * 2048 * 512];
__device__ __half g_vT  [(size_t)48 * 512 * 2048];
__device__ __half g_sc  [(size_t)48 * 512 * 2048];
__device__ __half g_att [(size_t)48 * 512 * 512];
__device__ float  g_x   [(size_t)48 * 512 * 512];             // fp32 residual
__device__ __half g_xn  [(size_t)48 * 512 * 512];
__device__ __half g_h   [(size_t)24576 * 4096];
__device__ __half g_ag  [(size_t)24576 * 2048];
__device__ __half g_wc  [4194304];   // wqT|wkT|wvT|woT|w1T|w2T  ([N][K] half)

// ------------------------- helpers -----------------------------------------
__device__ __forceinline__ void cp16(void* dst, const void* src) {
    unsigned d = (unsigned)__cvta_generic_to_shared(dst);
    asm volatile("cp.async.cg.shared.global [%0], [%1], 16;" :: "r"(d), "l"(src));
}

__device__ __forceinline__ void mma16(float* d, const unsigned* a, const unsigned* b) {
    asm volatile(
        "mma.sync.aligned.m16n8k16.row.col.f32.f16.f16.f32 "
        "{%0,%1,%2,%3}, {%4,%5,%6,%7}, {%8,%9}, {%0,%1,%2,%3};"
        : "+f"(d[0]), "+f"(d[1]), "+f"(d[2]), "+f"(d[3])
        : "r"(a[0]), "r"(a[1]), "r"(a[2]), "r"(a[3]), "r"(b[0]), "r"(b[1]));
}

__device__ __forceinline__ float blockReduceSum(float v, float* red) {
    #pragma unroll
    for (int o = 16; o; o >>= 1) v += __shfl_down_sync(0xffffffffu, v, o);
    int lane = threadIdx.x & 31, w = threadIdx.x >> 5;
    if (lane == 0) red[w] = v;
    __syncthreads();
    if (threadIdx.x < 32) {
        float s = (threadIdx.x < (blockDim.x >> 5)) ? red[threadIdx.x] : 0.0f;
        #pragma unroll
        for (int o = 16; o; o >>= 1) s += __shfl_down_sync(0xffffffffu, s, o);
        if (threadIdx.x == 0) red[0] = s;
    }
    __syncthreads();
    float r = red[0];
    __syncthreads();
    return r;
}

__device__ __forceinline__ float blockReduceMax(float v, float* red) {
    #pragma unroll
    for (int o = 16; o; o >>= 1) v = fmaxf(v, __shfl_down_sync(0xffffffffu, v, o));
    int lane = threadIdx.x & 31, w = threadIdx.x >> 5;
    if (lane == 0) red[w] = v;
    __syncthreads();
    if (threadIdx.x < 32) {
        float s = (threadIdx.x < (blockDim.x >> 5)) ? red[threadIdx.x] : -3.0e38f;
        #pragma unroll
        for (int o = 16; o; o >>= 1) s = fmaxf(s, __shfl_down_sync(0xffffffffu, s, o));
        if (threadIdx.x == 0) red[0] = s;
    }
    __syncthreads();
    float r = red[0];
    __syncthreads();
    return r;
}

// ------------------------- FPS ----------------------------------------------
__global__ void fps_kernel(const float* __restrict__ pc, int* __restrict__ idx) {
    int b = blockIdx.x;
    int t = threadIdx.x;
    const float* pts = pc + (size_t)b * 3 * 2048 * 3;
    int t1 = t + 1024;
    float x0 = pts[t * 3 + 0], y0 = pts[t * 3 + 1], z0 = pts[t * 3 + 2];
    float x1 = pts[t1 * 3 + 0], y1 = pts[t1 * 3 + 1], z1 = pts[t1 * 3 + 2];
    float d0 = 1e10f, d1 = 1e10f;

    __shared__ float lx, ly, lz;
    __shared__ float sv[32];
    __shared__ int   si[32];
    if (t == 0) { lx = pts[0]; ly = pts[1]; lz = pts[2]; idx[b * 512] = 0; }
    __syncthreads();

    for (int s = 1; s < 512; s++) {
        float ax = __fadd_rn(x0, -lx), ay = __fadd_rn(y0, -ly), az = __fadd_rn(z0, -lz);
        float e0 = __fadd_rn(__fadd_rn(__fmul_rn(ax, ax), __fmul_rn(ay, ay)), __fmul_rn(az, az));
        float bx = __fadd_rn(x1, -lx), by = __fadd_rn(y1, -ly), bz = __fadd_rn(z1, -lz);
        float e1 = __fadd_rn(__fadd_rn(__fmul_rn(bx, bx), __fmul_rn(by, by)), __fmul_rn(bz, bz));
        d0 = fminf(d0, e0);
        d1 = fminf(d1, e1);

        float v;
        int   vi;
        if (d1 > d0) { v = d1; vi = t1; } else { v = d0; vi = t; }
        #pragma unroll
        for (int o = 16; o; o >>= 1) {
            float ov = __shfl_down_sync(0xffffffffu, v, o);
            int   oi = __shfl_down_sync(0xffffffffu, vi, o);
            if (ov > v || (ov == v && oi < vi)) { v = ov; vi = oi; }
        }
        int lane = t & 31, w = t >> 5;
        if (lane == 0) { sv[w] = v; si[w] = vi; }
        __syncthreads();
        if (t < 32) {
            v = sv[t]; vi = si[t];
            #pragma unroll
            for (int o = 16; o; o >>= 1) {
                float ov = __shfl_down_sync(0xffffffffu, v, o);
                int   oi = __shfl_down_sync(0xffffffffu, vi, o);
                if (ov > v || (ov == v && oi < vi)) { v = ov; vi = oi; }
            }
            if (t == 0) {
                idx[b * 512 + s] = vi;
                lx = pts[vi * 3 + 0]; ly = pts[vi * 3 + 1]; lz = pts[vi * 3 + 2];
            }
        }
        __syncthreads();
    }
}

// ------------------------- fused point-embed + LayerNorm --------------------
template <bool GATHER>
__global__ void embed_ln_kernel(const float* __restrict__ pc, const float* __restrict__ pc2,
                                const float* __restrict__ basis,
                                const float* __restrict__ pe_w, const float* __restrict__ pe_b,
                                const float* __restrict__ lng, const float* __restrict__ lnb,
                                const int* __restrict__ idx,
                                float* __restrict__ emb_out, __half* __restrict__ ln_out) {
    const int j = threadIdx.x;
    const int half_ = j >> 8;
    const int col  = j & 255;
    float w[51];
    #pragma unroll
    for (int i = 0; i < 51; i++) w[i] = pe_w[i * 256 + col];
    const float pb = pe_b[col];
    const float gj = lng[j], bj = lnb[j];

    __shared__ float sx[2][3];
    __shared__ float sf[2][51];
    __shared__ float red[32];

    for (int p = 0; p < 8; p++) {
        long row = (long)blockIdx.x * 8 + p;
        long bt, n;
        if (GATHER) {
            bt = row >> 9;
            int m = (int)(row & 511);
            int b = (int)(bt / 3);
            n = idx[b * 512 + m];
        } else {
            bt = row >> 11;
            n = row & 2047;
        }
        size_t base = ((size_t)bt * 2048 + (size_t)n) * 3;
        if (j < 3)           sx[0][j]     = pc[base + j];
        else if (j < 6)      sx[1][j - 3] = pc2[base + j - 3];
        __syncthreads();

        if (j < 24) {
            float pr = sx[0][0] * basis[j] + sx[0][1] * basis[24 + j] + sx[0][2] * basis[48 + j];
            sf[0][j] = sinf(pr);
            sf[0][24 + j] = cosf(pr);
        } else if (j >= 32 && j < 56) {
            int e = j - 32;
            float pr = sx[1][0] * basis[e] + sx[1][1] * basis[24 + e] + sx[1][2] * basis[48 + e];
            sf[1][e] = sinf(pr);
            sf[1][24 + e] = cosf(pr);
        } else if (j >= 64 && j < 67) {
            sf[0][48 + (j - 64)] = sx[0][j - 64];
        } else if (j >= 67 && j < 70) {
            sf[1][48 + (j - 67)] = sx[1][j - 67];
        }
        __syncthreads();

        float acc = pb;
        #pragma unroll
        for (int i = 0; i < 51; i++) acc += w[i] * sf[half_][i];

        float mean = blockReduceSum(acc, red) * (1.0f / 512.0f);
        float d = acc - mean;
        float var = blockReduceSum(d * d, red) * (1.0f / 512.0f);
        float ln = d * rsqrtf(var + 1e-5f) * gj + bj;

        size_t o = (size_t)row * 512 + j;
        if (GATHER) emb_out[o] = acc;
        ln_out[o] = __float2half_rn(ln);
        __syncthreads();
    }
}

// ------------------------- fp16 tensor-core NT GEMM -------------------------
// C[M,N] = A[M,K] @ B[N,K]^T, fp16 in, fp32 accum.
// BM=BN=128, BK=32 (halves), 256 threads, 8 warps (2m x 4n), warp 64x32.
// EPI: 0 none, 1 +bias, 2 +bias+res(fp32).  OUTF: fp32 out else half out.
#define ASTR 40   // smem row stride in halves (conflict-free)

template <int EPI, bool OUTF>
__global__ void __launch_bounds__(256)
hgemm(const __half* __restrict__ A, const __half* __restrict__ B, void* __restrict__ Cv,
      int K, int ldc, size_t sA, size_t sB, size_t sC,
      const float* __restrict__ bias, const float* __restrict__ res) {
    __shared__ __align__(16) __half As[2][128 * ASTR];
    __shared__ __align__(16) __half Bs[2][128 * ASTR];

    const int t = threadIdx.x;
    const int lane = t & 31, wid = t >> 5;
    const size_t bm = (size_t)blockIdx.y * 128, bn = (size_t)blockIdx.x * 128;
    A += (size_t)blockIdx.z * sA + bm * (size_t)K;
    B += (size_t)blockIdx.z * sB + bn * (size_t)K;
    const float* resp = (EPI == 2) ? res + (size_t)blockIdx.z * sC : nullptr;

    const int wm = (wid >> 2) * 64, wn = (wid & 3) * 32;
    const int g = lane >> 2, tg = lane & 3;

    float acc[4][4][4];
    #pragma unroll
    for (int mi = 0; mi < 4; mi++)
        #pragma unroll
        for (int ni = 0; ni < 4; ni++)
            #pragma unroll
            for (int r = 0; r < 4; r++) acc[mi][ni][r] = 0.0f;

    const int T = K >> 5;
    const int lrow = t >> 2, lseg = (t & 3) * 8;

    auto issue = [&](int kt, int buf) {
        const __half* Ag = A + kt * 32;
        const __half* Bg = B + kt * 32;
        #pragma unroll
        for (int i = 0; i < 2; i++) {
            int row = lrow + i * 64;
            cp16(&As[buf][row * ASTR + lseg], Ag + (size_t)row * K + lseg);
            cp16(&Bs[buf][row * ASTR + lseg], Bg + (size_t)row * K + lseg);
        }
        asm volatile("cp.async.commit_group;");
    };

    issue(0, 0);
    for (int kt = 0; kt < T; kt++) {
        if (kt + 1 < T) {
            issue(kt + 1, (kt + 1) & 1);
            asm volatile("cp.async.wait_group 1;");
        } else {
            asm volatile("cp.async.wait_group 0;");
        }
        __syncthreads();

        const __half* Ab = As[kt & 1];
        const __half* Bb = Bs[kt & 1];

        #pragma unroll
        for (int ks = 0; ks < 2; ks++) {
            unsigned a[4][4], b[4][2];
            #pragma unroll
            for (int mi = 0; mi < 4; mi++) {
                const __half* p = Ab + (wm + mi * 16 + g) * ASTR + ks * 16 + tg * 2;
                a[mi][0] = *(const unsigned*)(p);
                a[mi][1] = *(const unsigned*)(p + 8 * ASTR);
                a[mi][2] = *(const unsigned*)(p + 8);
                a[mi][3] = *(const unsigned*)(p + 8 * ASTR + 8);
            }
            #pragma unroll
            for (int ni = 0; ni < 4; ni++) {
                const __half* p = Bb + (wn + ni * 8 + g) * ASTR + ks * 16 + tg * 2;
                b[ni][0] = *(const unsigned*)(p);
                b[ni][1] = *(const unsigned*)(p + 8);
            }
            #pragma unroll
            for (int mi = 0; mi < 4; mi++)
                #pragma unroll
                for (int ni = 0; ni < 4; ni++)
                    mma16(acc[mi][ni], a[mi], b[ni]);
        }
        __syncthreads();
    }

    // ---- epilogue ----
    float*  Cf = (float*)Cv;
    __half* Ch = (__half*)Cv;
    if (OUTF) Cf += (size_t)blockIdx.z * sC; else Ch += (size_t)blockIdx.z * sC;

    #pragma unroll
    for (int mi = 0; mi < 4; mi++) {
        size_t r = bm + wm + mi * 16 + g;
        #pragma unroll
        for (int ni = 0; ni < 4; ni++) {
            size_t c = bn + wn + ni * 8 + tg * 2;
            float v0 = acc[mi][ni][0], v1 = acc[mi][ni][1];
            float v2 = acc[mi][ni][2], v3 = acc[mi][ni][3];
            if (EPI >= 1) {
                float b0 = bias[c], b1 = bias[c + 1];
                v0 += b0; v1 += b1; v2 += b0; v3 += b1;
            }
            if (EPI == 2) {
                float2 r0v = *(const float2*)(resp + r * ldc + c);
                float2 r1v = *(const float2*)(resp + (r + 8) * ldc + c);
                v0 += r0v.x; v1 += r0v.y; v2 += r1v.x; v3 += r1v.y;
            }
            if (OUTF) {
                *(float2*)(Cf + r * ldc + c) = make_float2(v0, v1);
                *(float2*)(Cf + (r + 8) * ldc + c) = make_float2(v2, v3);
            } else {
                *(__half2*)(Ch + r * ldc + c) = __floats2half2_rn(v0, v1);
                *(__half2*)(Ch + (r + 8) * ldc + c) = __floats2half2_rn(v2, v3);
            }
        }
    }
}

// ------------------------- softmax (rows of 2048, half) ----------------------
__global__ void softmax_kernel(__half* __restrict__ s) {
    const size_t row = blockIdx.x;
    __half* p = s + row * 2048;
    const int t = threadIdx.x;
    const float scale = 0.044194173824159216f;
    __shared__ float red[32];
    float v[8];
    float mx = -3.0e38f;
    #pragma unroll
    for (int i = 0; i < 8; i++) {
        v[i] = __half2float(p[t + i * 256]) * scale;
        mx = fmaxf(mx, v[i]);
    }
    mx = blockReduceMax(mx, red);
    float sum = 0.0f;
    #pragma unroll
    for (int i = 0; i < 8; i++) {
        v[i] = expf(v[i] - mx);
        sum += v[i];
    }
    sum = blockReduceSum(sum, red);
    float inv = 1.0f / sum;
    #pragma unroll
    for (int i = 0; i < 8; i++) p[t + i * 256] = __float2half_rn(v[i] * inv);
}

// ------------------------- LayerNorm (512), fp32 in, half out ---------------
__global__ void ln_kernel(const float* __restrict__ x, __half* __restrict__ y,
                          const float* __restrict__ g, const float* __restrict__ b) {
    const size_t row = blockIdx.x;
    const int j = threadIdx.x;
    __shared__ float red[32];
    float v = x[row * 512 + j];
    float mean = blockReduceSum(v, red) * (1.0f / 512.0f);
    float d = v - mean;
    float var = blockReduceSum(d * d, red) * (1.0f / 512.0f);
    y[row * 512 + j] = __float2half_rn(d * rsqrtf(var + 1e-5f) * g[j] + b[j]);
}

// ------------------------- a * gelu(g), half -----------------------------------
__global__ void geluprod_kernel(const __half* __restrict__ h, __half* __restrict__ ag) {
    size_t i = (size_t)blockIdx.x * blockDim.x + threadIdx.x;
    size_t m = i >> 11, j = i & 2047;
    float a = __half2float(h[m * 4096 + j]);
    float gg = __half2float(h[m * 4096 + 2048 + j]);
    float ge = 0.5f * gg * (1.0f + erff(gg * 0.7071067811865475f));
    ag[i] = __float2half_rn(a * ge);
}

// ------------------------- transpose fp32 -> fp16 ----------------------------
// dst[c * R + r] = (half)src[r * ld + coff + c]
__global__ void transcvt_kernel(const float* __restrict__ src, __half* __restrict__ dst,
                                int R, int ld, int coff) {
    __shared__ float tile[32][33];
    int c0 = blockIdx.x * 32, r0 = blockIdx.y * 32;
    int tx = threadIdx.x & 31, ty = threadIdx.x >> 5;
    #pragma unroll
    for (int i = 0; i < 32; i += 8)
        tile[ty + i][tx] = src[(size_t)(r0 + ty + i) * ld + coff + c0 + tx];
    __syncthreads();
    #pragma unroll
    for (int i = 0; i < 32; i += 8)
        dst[(size_t)(c0 + ty + i) * R + r0 + tx] = __float2half_rn(tile[tx][ty + i]);
}

// ---------------------------------------------------------------------------
extern "C" void kernel_launch(void* const* d_in, const int* in_sizes, int n_in,
                              void* d_out, int out_size) {
    const float* pc    = (const float*)d_in[0];
    const float* pc2   = (const float*)d_in[1];
    const float* basis = (const float*)d_in[2];
    const float* pe_w  = (const float*)d_in[3];
    const float* pe_b  = (const float*)d_in[4];
    const float* lnq_g = (const float*)d_in[5];
    const float* lnq_b = (const float*)d_in[6];
    const float* lnc_g = (const float*)d_in[7];
    const float* lnc_b = (const float*)d_in[8];
    const float* wq    = (const float*)d_in[9];
    const float* wkv   = (const float*)d_in[10];
    const float* wo    = (const float*)d_in[11];
    const float* bo    = (const float*)d_in[12];
    const float* lnf_g = (const float*)d_in[13];
    const float* lnf_b = (const float*)d_in[14];
    const float* w1    = (const float*)d_in[15];
    const float* b1    = (const float*)d_in[16];
    const float* w2    = (const float*)d_in[17];
    const float* b2    = (const float*)d_in[18];
    float* out = (float*)d_out;

    void *vp;
    int*    p_idx;  cudaGetSymbolAddress(&vp, g_idx);   p_idx  = (int*)vp;
    float*  p_embs; cudaGetSymbolAddress(&vp, g_emb_s); p_embs = (float*)vp;
    __half* p_lnq;  cudaGetSymbolAddress(&vp, g_lnq);   p_lnq  = (__half*)vp;
    __half* p_lnc;  cudaGetSymbolAddress(&vp, g_lnc);   p_lnc  = (__half*)vp;
    __half* p_q;    cudaGetSymbolAddress(&vp, g_q);     p_q    = (__half*)vp;
    __half* p_k;    cudaGetSymbolAddress(&vp, g_k);     p_k    = (__half*)vp;
    __half* p_vT;   cudaGetSymbolAddress(&vp, g_vT);    p_vT   = (__half*)vp;
    __half* p_sc;   cudaGetSymbolAddress(&vp, g_sc);    p_sc   = (__half*)vp;
    __half* p_att;  cudaGetSymbolAddress(&vp, g_att);   p_att  = (__half*)vp;
    float*  p_x;    cudaGetSymbolAddress(&vp, g_x);     p_x    = (float*)vp;
    __half* p_xn;   cudaGetSymbolAddress(&vp, g_xn);    p_xn   = (__half*)vp;
    __half* p_h;    cudaGetSymbolAddress(&vp, g_h);     p_h    = (__half*)vp;
    __half* p_ag;   cudaGetSymbolAddress(&vp, g_ag);    p_ag   = (__half*)vp;
    __half* p_wc;   cudaGetSymbolAddress(&vp, g_wc);    p_wc   = (__half*)vp;

    __half* wqT = p_wc;                 // [512,512]
    __half* wkT = p_wc + 262144;        // [512,512]
    __half* wvT = p_wc + 524288;        // [512,512]
    __half* woT = p_wc + 786432;        // [512,512]
    __half* w1T = p_wc + 1048576;       // [4096,512]
    __half* w2T = p_wc + 3145728;       // [512,2048]

    // 0) weight transpose + fp16 convert
    transcvt_kernel<<<dim3(16, 16), 256>>>(wq,  wqT, 512, 512, 0);
    transcvt_kernel<<<dim3(16, 16), 256>>>(wkv, wkT, 512, 1024, 0);
    transcvt_kernel<<<dim3(16, 16), 256>>>(wkv, wvT, 512, 1024, 512);
    transcvt_kernel<<<dim3(16, 16), 256>>>(wo,  woT, 512, 512, 0);
    transcvt_kernel<<<dim3(128, 16), 256>>>(w1, w1T, 512, 4096, 0);
    transcvt_kernel<<<dim3(16, 64), 256>>>(w2, w2T, 2048, 512, 0);

    // 1) FPS
    fps_kernel<<<16, 1024>>>(pc, p_idx);

    // 2) fused embed + LN (half outputs for GEMM A sides)
    embed_ln_kernel<true ><<<48 * 512 / 8, 512>>>(pc, pc2, basis, pe_w, pe_b,
                                                  lnq_g, lnq_b, p_idx, p_embs, p_lnq);
    embed_ln_kernel<false><<<48 * 2048 / 8, 512>>>(pc, pc2, basis, pe_w, pe_b,
                                                   lnc_g, lnc_b, nullptr, nullptr, p_lnc);

    // 3) q = lnq @ wqT^T               M=24576 N=512 K=512
    hgemm<0, false><<<dim3(4, 192, 1), 256>>>(
        p_lnq, wqT, p_q, 512, 512, 0, 0, 0, nullptr, nullptr);

    // 4) k = lnc @ wkT^T               M=98304 N=512 K=512
    hgemm<0, false><<<dim3(4, 768, 1), 256>>>(
        p_lnc, wkT, p_k, 512, 512, 0, 0, 0, nullptr, nullptr);

    // 5) vT[b] = wvT @ lnc[b]^T        M=512 N=2048 K=512, batched 48
    hgemm<0, false><<<dim3(16, 4, 48), 256>>>(
        wvT, p_lnc, p_vT, 512, 2048, 0, (size_t)2048 * 512, (size_t)512 * 2048,
        nullptr, nullptr);

    // 6) sc[b] = q[b] @ k[b]^T         M=512 N=2048 K=512, batched 48
    hgemm<0, false><<<dim3(16, 4, 48), 256>>>(
        p_q, p_k, p_sc, 512, 2048, (size_t)512 * 512, (size_t)2048 * 512,
        (size_t)512 * 2048, nullptr, nullptr);

    // 7) softmax
    softmax_kernel<<<24576, 256>>>(p_sc);

    // 8) att[b] = sc[b] @ vT[b]^T      M=512 N=512 K=2048, batched 48
    hgemm<0, false><<<dim3(4, 4, 48), 256>>>(
        p_sc, p_vT, p_att, 2048, 512, (size_t)512 * 2048, (size_t)512 * 2048,
        (size_t)512 * 512, nullptr, nullptr);

    // 9) x = att @ woT^T + bo + emb_s  (fp32 out)
    hgemm<2, true><<<dim3(4, 192, 1), 256>>>(
        p_att, woT, p_x, 512, 512, 0, 0, 0, bo, p_embs);

    // 10) xn = LN(x)
    ln_kernel<<<24576, 512>>>(p_x, p_xn, lnf_g, lnf_b);

    // 11) h = xn @ w1T^T + b1          M=24576 N=4096 K=512
    hgemm<1, false><<<dim3(32, 192, 1), 256>>>(
        p_xn, w1T, p_h, 512, 4096, 0, 0, 0, b1, nullptr);

    // 12) ag = a * gelu(g)
    geluprod_kernel<<<(24576 * 2048) / 256, 256>>>(p_h, p_ag);

    // 13) out = ag @ w2T^T + b2 + x    M=24576 N=512 K=2048 (fp32 out)
    hgemm<2, true><<<dim3(4, 192, 1), 256>>>(
        p_ag, w2T, out, 2048, 512, 0, 0, 0, b2, p_x);
}

// round 5
// speedup vs baseline: 3.4802x; 1.1584x over previous
#include <cuda_runtime.h>
#include <cuda_fp16.h>
#include <math.h>
#include <stdint.h>

// ---------------------------------------------------------------------------
// B=16, T=3, N=2048, D=3, NUM_LATENTS=512, DIM=512, HIDDEN=48 (k=8), BT=48
// All GEMMs NT: C[M,N] = A[M,K] @ B[N,K]^T, fp16 in, fp32 accum,
// mma.sync.m16n8k16 + ldmatrix.x4, BK=64, 3-stage cp.async pipeline.
// FFN1 GELU fused into GEMM epilogue via interleaved w1T rows.
// ---------------------------------------------------------------------------

// ------------------------- scratch (device globals) ------------------------
__device__ int    g_idx[16 * 512];
__device__ float  g_emb_s[(size_t)48 * 512 * 512];
__device__ __half g_lnq [(size_t)48 * 512 * 512];
__device__ __half g_lnc [(size_t)48 * 2048 * 512];
__device__ __half g_q   [(size_t)48 * 512 * 512];
__device__ __half g_k   [(size_t)48 * 2048 * 512];
__device__ __half g_vT  [(size_t)48 * 512 * 2048];
__device__ __half g_sc  [(size_t)48 * 512 * 2048];
__device__ __half g_att [(size_t)48 * 512 * 512];
__device__ float  g_x   [(size_t)48 * 512 * 512];
__device__ __half g_xn  [(size_t)48 * 512 * 512];
__device__ __half g_ag  [(size_t)24576 * 2048];
__device__ __half g_wc  [4194304];   // wqT|wkT|wvT|woT|w1Ti|w2T

// ------------------------- helpers -----------------------------------------
__device__ __forceinline__ void cp16(void* dst, const void* src) {
    unsigned d = (unsigned)__cvta_generic_to_shared(dst);
    asm volatile("cp.async.cg.shared.global [%0], [%1], 16;" :: "r"(d), "l"(src));
}

__device__ __forceinline__ void ldsm4(unsigned* r, uint32_t a) {
    asm volatile("ldmatrix.sync.aligned.m8n8.x4.shared.b16 {%0,%1,%2,%3}, [%4];"
                 : "=r"(r[0]), "=r"(r[1]), "=r"(r[2]), "=r"(r[3]) : "r"(a));
}

__device__ __forceinline__ void mma16(float* d, const unsigned* a, unsigned b0, unsigned b1) {
    asm volatile(
        "mma.sync.aligned.m16n8k16.row.col.f32.f16.f16.f32 "
        "{%0,%1,%2,%3}, {%4,%5,%6,%7}, {%8,%9}, {%0,%1,%2,%3};"
        : "+f"(d[0]), "+f"(d[1]), "+f"(d[2]), "+f"(d[3])
        : "r"(a[0]), "r"(a[1]), "r"(a[2]), "r"(a[3]), "r"(b0), "r"(b1));
}

__device__ __forceinline__ uint32_t smem_u32(const void* p) {
    uint32_t a;
    asm("{ .reg .u64 t; cvta.to.shared.u64 t, %1; cvt.u32.u64 %0, t; }" : "=r"(a) : "l"(p));
    return a;
}

__device__ __forceinline__ float blockReduceSum(float v, float* red) {
    #pragma unroll
    for (int o = 16; o; o >>= 1) v += __shfl_down_sync(0xffffffffu, v, o);
    int lane = threadIdx.x & 31, w = threadIdx.x >> 5;
    if (lane == 0) red[w] = v;
    __syncthreads();
    if (threadIdx.x < 32) {
        float s = (threadIdx.x < (blockDim.x >> 5)) ? red[threadIdx.x] : 0.0f;
        #pragma unroll
        for (int o = 16; o; o >>= 1) s += __shfl_down_sync(0xffffffffu, s, o);
        if (threadIdx.x == 0) red[0] = s;
    }
    __syncthreads();
    float r = red[0];
    __syncthreads();
    return r;
}

__device__ __forceinline__ float blockReduceMax(float v, float* red) {
    #pragma unroll
    for (int o = 16; o; o >>= 1) v = fmaxf(v, __shfl_down_sync(0xffffffffu, v, o));
    int lane = threadIdx.x & 31, w = threadIdx.x >> 5;
    if (lane == 0) red[w] = v;
    __syncthreads();
    if (threadIdx.x < 32) {
        float s = (threadIdx.x < (blockDim.x >> 5)) ? red[threadIdx.x] : -3.0e38f;
        #pragma unroll
        for (int o = 16; o; o >>= 1) s = fmaxf(s, __shfl_down_sync(0xffffffffu, s, o));
        if (threadIdx.x == 0) red[0] = s;
    }
    __syncthreads();
    float r = red[0];
    __syncthreads();
    return r;
}

// ------------------------- FPS ----------------------------------------------
__global__ void fps_kernel(const float* __restrict__ pc, int* __restrict__ idx) {
    int b = blockIdx.x;
    int t = threadIdx.x;
    const float* pts = pc + (size_t)b * 3 * 2048 * 3;
    int t1 = t + 1024;
    float x0 = pts[t * 3 + 0], y0 = pts[t * 3 + 1], z0 = pts[t * 3 + 2];
    float x1 = pts[t1 * 3 + 0], y1 = pts[t1 * 3 + 1], z1 = pts[t1 * 3 + 2];
    float d0 = 1e10f, d1 = 1e10f;

    __shared__ float lx, ly, lz;
    __shared__ float sv[32];
    __shared__ int   si[32];
    if (t == 0) { lx = pts[0]; ly = pts[1]; lz = pts[2]; idx[b * 512] = 0; }
    __syncthreads();

    for (int s = 1; s < 512; s++) {
        float ax = __fadd_rn(x0, -lx), ay = __fadd_rn(y0, -ly), az = __fadd_rn(z0, -lz);
        float e0 = __fadd_rn(__fadd_rn(__fmul_rn(ax, ax), __fmul_rn(ay, ay)), __fmul_rn(az, az));
        float bx = __fadd_rn(x1, -lx), by = __fadd_rn(y1, -ly), bz = __fadd_rn(z1, -lz);
        float e1 = __fadd_rn(__fadd_rn(__fmul_rn(bx, bx), __fmul_rn(by, by)), __fmul_rn(bz, bz));
        d0 = fminf(d0, e0);
        d1 = fminf(d1, e1);

        float v;
        int   vi;
        if (d1 > d0) { v = d1; vi = t1; } else { v = d0; vi = t; }
        #pragma unroll
        for (int o = 16; o; o >>= 1) {
            float ov = __shfl_down_sync(0xffffffffu, v, o);
            int   oi = __shfl_down_sync(0xffffffffu, vi, o);
            if (ov > v || (ov == v && oi < vi)) { v = ov; vi = oi; }
        }
        int lane = t & 31, w = t >> 5;
        if (lane == 0) { sv[w] = v; si[w] = vi; }
        __syncthreads();
        if (t < 32) {
            v = sv[t]; vi = si[t];
            #pragma unroll
            for (int o = 16; o; o >>= 1) {
                float ov = __shfl_down_sync(0xffffffffu, v, o);
                int   oi = __shfl_down_sync(0xffffffffu, vi, o);
                if (ov > v || (ov == v && oi < vi)) { v = ov; vi = oi; }
            }
            if (t == 0) {
                idx[b * 512 + s] = vi;
                lx = pts[vi * 3 + 0]; ly = pts[vi * 3 + 1]; lz = pts[vi * 3 + 2];
            }
        }
        __syncthreads();
    }
}

// ------------------------- fused point-embed + LayerNorm --------------------
template <bool GATHER>
__global__ void embed_ln_kernel(const float* __restrict__ pc, const float* __restrict__ pc2,
                                const float* __restrict__ basis,
                                const float* __restrict__ pe_w, const float* __restrict__ pe_b,
                                const float* __restrict__ lng, const float* __restrict__ lnb,
                                const int* __restrict__ idx,
                                float* __restrict__ emb_out, __half* __restrict__ ln_out) {
    const int j = threadIdx.x;
    const int half_ = j >> 8;
    const int col  = j & 255;
    float w[51];
    #pragma unroll
    for (int i = 0; i < 51; i++) w[i] = pe_w[i * 256 + col];
    const float pb = pe_b[col];
    const float gj = lng[j], bj = lnb[j];

    __shared__ float sx[2][3];
    __shared__ float sf[2][51];
    __shared__ float red[32];

    for (int p = 0; p < 8; p++) {
        long row = (long)blockIdx.x * 8 + p;
        long bt, n;
        if (GATHER) {
            bt = row >> 9;
            int m = (int)(row & 511);
            int b = (int)(bt / 3);
            n = idx[b * 512 + m];
        } else {
            bt = row >> 11;
            n = row & 2047;
        }
        size_t base = ((size_t)bt * 2048 + (size_t)n) * 3;
        if (j < 3)           sx[0][j]     = pc[base + j];
        else if (j < 6)      sx[1][j - 3] = pc2[base + j - 3];
        __syncthreads();

        if (j < 24) {
            float pr = sx[0][0] * basis[j] + sx[0][1] * basis[24 + j] + sx[0][2] * basis[48 + j];
            sf[0][j] = sinf(pr);
            sf[0][24 + j] = cosf(pr);
        } else if (j >= 32 && j < 56) {
            int e = j - 32;
            float pr = sx[1][0] * basis[e] + sx[1][1] * basis[24 + e] + sx[1][2] * basis[48 + e];
            sf[1][e] = sinf(pr);
            sf[1][24 + e] = cosf(pr);
        } else if (j >= 64 && j < 67) {
            sf[0][48 + (j - 64)] = sx[0][j - 64];
        } else if (j >= 67 && j < 70) {
            sf[1][48 + (j - 67)] = sx[1][j - 67];
        }
        __syncthreads();

        float acc = pb;
        #pragma unroll
        for (int i = 0; i < 51; i++) acc += w[i] * sf[half_][i];

        float mean = blockReduceSum(acc, red) * (1.0f / 512.0f);
        float d = acc - mean;
        float var = blockReduceSum(d * d, red) * (1.0f / 512.0f);
        float ln = d * rsqrtf(var + 1e-5f) * gj + bj;

        size_t o = (size_t)row * 512 + j;
        if (GATHER) emb_out[o] = acc;
        ln_out[o] = __float2half_rn(ln);
        __syncthreads();
    }
}

// ------------------------- fp16 tensor-core NT GEMM (v2) --------------------
// BM=BN=128, BK=64 halves, 256 threads, 8 warps (2m x 4n), warp 64x32.
// ldmatrix.x4 fragment loads, 3-stage cp.async pipeline.
// EPI: 0 none(half out), 2 +bias+res -> fp32 out, 3 gelu-pair -> half out.
#define ASTR 72                       // smem row stride (halves)
#define TSZ  (128 * ASTR)             // halves per tile per stage
#define TSB  (TSZ * 2)                // bytes per tile per stage
#define GSM  (6 * TSB)                // 3 stages x (A + B) = 110592 B

template <int EPI>
__global__ void __launch_bounds__(256)
hgemm(const __half* __restrict__ A, const __half* __restrict__ B, void* __restrict__ Cv,
      int K, int ldc, size_t sA, size_t sB, size_t sC,
      const float* __restrict__ bias, const float* __restrict__ res) {
    extern __shared__ __half sm[];
    __half* Asm = sm;            // 3 stages
    __half* Bsm = sm + 3 * TSZ;  // 3 stages

    const int t = threadIdx.x;
    const int lane = t & 31, wid = t >> 5;
    const size_t bm = (size_t)blockIdx.y * 128, bn = (size_t)blockIdx.x * 128;
    A += (size_t)blockIdx.z * sA + bm * (size_t)K;
    B += (size_t)blockIdx.z * sB + bn * (size_t)K;
    const float* resp = (EPI == 2) ? res + (size_t)blockIdx.z * sC : nullptr;

    const int wm = (wid >> 2) * 64, wn = (wid & 3) * 32;
    const int g = lane >> 2, tg = lane & 3;

    float acc[4][4][4];
    #pragma unroll
    for (int mi = 0; mi < 4; mi++)
        #pragma unroll
        for (int ni = 0; ni < 4; ni++)
            #pragma unroll
            for (int r = 0; r < 4; r++) acc[mi][ni][r] = 0.0f;

    const int T = K >> 6;
    const int lrow = t >> 2, lseg = (t & 3) * 16;      // cp: rows t>>2? (see below)

    // cp.async mapping: 1024 16B-segments per tile; thread does 4.
    // seg = t + 256*i ; row = seg>>3 ; halfoff = (seg&7)*8
    auto issue = [&](int kt) {
        const int s = kt % 3;
        const __half* Ag = A + kt * 64;
        const __half* Bg = B + kt * 64;
        __half* Ab = Asm + s * TSZ;
        __half* Bb = Bsm + s * TSZ;
        #pragma unroll
        for (int i = 0; i < 4; i++) {
            int seg = t + 256 * i;
            int row = seg >> 3, ho = (seg & 7) * 8;
            cp16(Ab + row * ASTR + ho, Ag + (size_t)row * K + ho);
            cp16(Bb + row * ASTR + ho, Bg + (size_t)row * K + ho);
        }
        asm volatile("cp.async.commit_group;");
    };

    // ldmatrix lane addressing
    const int lr16 = lane & 15, lc8 = (lane >> 4) * 8;
    const uint32_t aU = smem_u32(Asm) + (uint32_t)(((wm + lr16) * ASTR + lc8) * 2);
    const uint32_t bU = smem_u32(Bsm) + (uint32_t)(((wn + lr16) * ASTR + lc8) * 2);

    issue(0);
    issue(1);
    for (int kt = 0; kt < T; kt++) {
        if (kt + 2 < T) issue(kt + 2);
        else asm volatile("cp.async.commit_group;");
        asm volatile("cp.async.wait_group 2;");
        __syncthreads();

        const uint32_t as = aU + (uint32_t)((kt % 3) * TSB);
        const uint32_t bs = bU + (uint32_t)((kt % 3) * TSB);

        #pragma unroll
        for (int ks = 0; ks < 4; ks++) {
            unsigned af[4][4], bf[2][4];
            #pragma unroll
            for (int mi = 0; mi < 4; mi++)
                ldsm4(af[mi], as + (uint32_t)((mi * 16 * ASTR + ks * 16) * 2));
            #pragma unroll
            for (int p = 0; p < 2; p++)
                ldsm4(bf[p], bs + (uint32_t)((p * 16 * ASTR + ks * 16) * 2));
            #pragma unroll
            for (int mi = 0; mi < 4; mi++) {
                #pragma unroll
                for (int p = 0; p < 2; p++) {
                    mma16(acc[mi][2 * p + 0], af[mi], bf[p][0], bf[p][2]);
                    mma16(acc[mi][2 * p + 1], af[mi], bf[p][1], bf[p][3]);
                }
            }
        }
        __syncthreads();
    }

    // ---- epilogue ----
    float*  Cf = (float*)Cv + ((EPI == 2) ? (size_t)blockIdx.z * sC : 0);
    __half* Ch = (__half*)Cv + ((EPI != 2) ? (size_t)blockIdx.z * sC : 0);

    #pragma unroll
    for (int mi = 0; mi < 4; mi++) {
        size_t r = bm + wm + mi * 16 + g;
        #pragma unroll
        for (int ni = 0; ni < 4; ni++) {
            size_t c = bn + wn + ni * 8 + tg * 2;
            float v0 = acc[mi][ni][0], v1 = acc[mi][ni][1];
            float v2 = acc[mi][ni][2], v3 = acc[mi][ni][3];
            if (EPI == 2) {
                float b0 = bias[c], b1 = bias[c + 1];
                float2 r0v = *(const float2*)(resp + r * ldc + c);
                float2 r1v = *(const float2*)(resp + (r + 8) * ldc + c);
                *(float2*)(Cf + r * ldc + c) = make_float2(v0 + b0 + r0v.x, v1 + b1 + r0v.y);
                *(float2*)(Cf + (r + 8) * ldc + c) = make_float2(v2 + b0 + r1v.x, v3 + b1 + r1v.y);
            } else if (EPI == 3) {
                // interleaved FFN1: even col = a_j, odd col = g_j ; j = c>>1
                size_t j = c >> 1;
                float ba = bias[j], bg = bias[j + 2048];
                float a0 = v0 + ba, g0 = v1 + bg;
                float a1 = v2 + ba, g1 = v3 + bg;
                float ge0 = 0.5f * g0 * (1.0f + erff(g0 * 0.7071067811865475f));
                float ge1 = 0.5f * g1 * (1.0f + erff(g1 * 0.7071067811865475f));
                Ch[r * ldc + j] = __float2half_rn(a0 * ge0);
                Ch[(r + 8) * ldc + j] = __float2half_rn(a1 * ge1);
            } else {
                *(__half2*)(Ch + r * ldc + c) = __floats2half2_rn(v0, v1);
                *(__half2*)(Ch + (r + 8) * ldc + c) = __floats2half2_rn(v2, v3);
            }
        }
    }
}

// ------------------------- softmax (rows of 2048, half) ----------------------
__global__ void softmax_kernel(__half* __restrict__ s) {
    const size_t row = blockIdx.x;
    __half* p = s + row * 2048;
    const int t = threadIdx.x;
    const float scale = 0.044194173824159216f;
    __shared__ float red[32];
    float v[8];
    float mx = -3.0e38f;
    #pragma unroll
    for (int i = 0; i < 8; i++) {
        v[i] = __half2float(p[t + i * 256]) * scale;
        mx = fmaxf(mx, v[i]);
    }
    mx = blockReduceMax(mx, red);
    float sum = 0.0f;
    #pragma unroll
    for (int i = 0; i < 8; i++) {
        v[i] = expf(v[i] - mx);
        sum += v[i];
    }
    sum = blockReduceSum(sum, red);
    float inv = 1.0f / sum;
    #pragma unroll
    for (int i = 0; i < 8; i++) p[t + i * 256] = __float2half_rn(v[i] * inv);
}

// ------------------------- LayerNorm (512), fp32 in, half out ---------------
__global__ void ln_kernel(const float* __restrict__ x, __half* __restrict__ y,
                          const float* __restrict__ g, const float* __restrict__ b) {
    const size_t row = blockIdx.x;
    const int j = threadIdx.x;
    __shared__ float red[32];
    float v = x[row * 512 + j];
    float mean = blockReduceSum(v, red) * (1.0f / 512.0f);
    float d = v - mean;
    float var = blockReduceSum(d * d, red) * (1.0f / 512.0f);
    y[row * 512 + j] = __float2half_rn(d * rsqrtf(var + 1e-5f) * g[j] + b[j]);
}

// ------------------------- transpose fp32 -> fp16 (optional interleave) -----
// dst[dr * R + r] = (half)src[r * ld + coff + c],
// dr = inter ? (c<inter ? 2c : 2(c-inter)+1) : c
__global__ void transcvt_kernel(const float* __restrict__ src, __half* __restrict__ dst,
                                int R, int ld, int coff, int inter) {
    __shared__ float tile[32][33];
    int c0 = blockIdx.x * 32, r0 = blockIdx.y * 32;
    int tx = threadIdx.x & 31, ty = threadIdx.x >> 5;
    #pragma unroll
    for (int i = 0; i < 32; i += 8)
        tile[ty + i][tx] = src[(size_t)(r0 + ty + i) * ld + coff + c0 + tx];
    __syncthreads();
    #pragma unroll
    for (int i = 0; i < 32; i += 8) {
        int c = c0 + ty + i;
        int dr = inter ? ((c < inter) ? 2 * c : 2 * (c - inter) + 1) : c;
        dst[(size_t)dr * R + r0 + tx] = __float2half_rn(tile[tx][ty + i]);
    }
}

// ---------------------------------------------------------------------------
extern "C" void kernel_launch(void* const* d_in, const int* in_sizes, int n_in,
                              void* d_out, int out_size) {
    const float* pc    = (const float*)d_in[0];
    const float* pc2   = (const float*)d_in[1];
    const float* basis = (const float*)d_in[2];
    const float* pe_w  = (const float*)d_in[3];
    const float* pe_b  = (const float*)d_in[4];
    const float* lnq_g = (const float*)d_in[5];
    const float* lnq_b = (const float*)d_in[6];
    const float* lnc_g = (const float*)d_in[7];
    const float* lnc_b = (const float*)d_in[8];
    const float* wq    = (const float*)d_in[9];
    const float* wkv   = (const float*)d_in[10];
    const float* wo    = (const float*)d_in[11];
    const float* bo    = (const float*)d_in[12];
    const float* lnf_g = (const float*)d_in[13];
    const float* lnf_b = (const float*)d_in[14];
    const float* w1    = (const float*)d_in[15];
    const float* b1    = (const float*)d_in[16];
    const float* w2    = (const float*)d_in[17];
    const float* b2    = (const float*)d_in[18];
    float* out = (float*)d_out;

    void *vp;
    int*    p_idx;  cudaGetSymbolAddress(&vp, g_idx);   p_idx  = (int*)vp;
    float*  p_embs; cudaGetSymbolAddress(&vp, g_emb_s); p_embs = (float*)vp;
    __half* p_lnq;  cudaGetSymbolAddress(&vp, g_lnq);   p_lnq  = (__half*)vp;
    __half* p_lnc;  cudaGetSymbolAddress(&vp, g_lnc);   p_lnc  = (__half*)vp;
    __half* p_q;    cudaGetSymbolAddress(&vp, g_q);     p_q    = (__half*)vp;
    __half* p_k;    cudaGetSymbolAddress(&vp, g_k);     p_k    = (__half*)vp;
    __half* p_vT;   cudaGetSymbolAddress(&vp, g_vT);    p_vT   = (__half*)vp;
    __half* p_sc;   cudaGetSymbolAddress(&vp, g_sc);    p_sc   = (__half*)vp;
    __half* p_att;  cudaGetSymbolAddress(&vp, g_att);   p_att  = (__half*)vp;
    float*  p_x;    cudaGetSymbolAddress(&vp, g_x);     p_x    = (float*)vp;
    __half* p_xn;   cudaGetSymbolAddress(&vp, g_xn);    p_xn   = (__half*)vp;
    __half* p_ag;   cudaGetSymbolAddress(&vp, g_ag);    p_ag   = (__half*)vp;
    __half* p_wc;   cudaGetSymbolAddress(&vp, g_wc);    p_wc   = (__half*)vp;

    __half* wqT  = p_wc;                 // [512,512]
    __half* wkT  = p_wc + 262144;        // [512,512]
    __half* wvT  = p_wc + 524288;        // [512,512]
    __half* woT  = p_wc + 786432;        // [512,512]
    __half* w1Ti = p_wc + 1048576;       // [4096,512] interleaved a/g
    __half* w2T  = p_wc + 3145728;       // [512,2048]

    cudaFuncSetAttribute(hgemm<0>, cudaFuncAttributeMaxDynamicSharedMemorySize, GSM);
    cudaFuncSetAttribute(hgemm<2>, cudaFuncAttributeMaxDynamicSharedMemorySize, GSM);
    cudaFuncSetAttribute(hgemm<3>, cudaFuncAttributeMaxDynamicSharedMemorySize, GSM);

    // 0) weight transpose + fp16 convert (w1 interleaved a/g)
    transcvt_kernel<<<dim3(16, 16), 256>>>(wq,  wqT, 512, 512, 0, 0);
    transcvt_kernel<<<dim3(16, 16), 256>>>(wkv, wkT, 512, 1024, 0, 0);
    transcvt_kernel<<<dim3(16, 16), 256>>>(wkv, wvT, 512, 1024, 512, 0);
    transcvt_kernel<<<dim3(16, 16), 256>>>(wo,  woT, 512, 512, 0, 0);
    transcvt_kernel<<<dim3(128, 16), 256>>>(w1, w1Ti, 512, 4096, 0, 2048);
    transcvt_kernel<<<dim3(16, 64), 256>>>(w2, w2T, 2048, 512, 0, 0);

    // 1) FPS
    fps_kernel<<<16, 1024>>>(pc, p_idx);

    // 2) fused embed + LN
    embed_ln_kernel<true ><<<48 * 512 / 8, 512>>>(pc, pc2, basis, pe_w, pe_b,
                                                  lnq_g, lnq_b, p_idx, p_embs, p_lnq);
    embed_ln_kernel<false><<<48 * 2048 / 8, 512>>>(pc, pc2, basis, pe_w, pe_b,
                                                   lnc_g, lnc_b, nullptr, nullptr, p_lnc);

    // 3) q = lnq @ wqT^T               M=24576 N=512 K=512
    hgemm<0><<<dim3(4, 192, 1), 256, GSM>>>(
        p_lnq, wqT, p_q, 512, 512, 0, 0, 0, nullptr, nullptr);

    // 4) k = lnc @ wkT^T               M=98304 N=512 K=512
    hgemm<0><<<dim3(4, 768, 1), 256, GSM>>>(
        p_lnc, wkT, p_k, 512, 512, 0, 0, 0, nullptr, nullptr);

    // 5) vT[b] = wvT @ lnc[b]^T        M=512 N=2048 K=512, batched 48
    hgemm<0><<<dim3(16, 4, 48), 256, GSM>>>(
        wvT, p_lnc, p_vT, 512, 2048, 0, (size_t)2048 * 512, (size_t)512 * 2048,
        nullptr, nullptr);

    // 6) sc[b] = q[b] @ k[b]^T         M=512 N=2048 K=512, batched 48
    hgemm<0><<<dim3(16, 4, 48), 256, GSM>>>(
        p_q, p_k, p_sc, 512, 2048, (size_t)512 * 512, (size_t)2048 * 512,
        (size_t)512 * 2048, nullptr, nullptr);

    // 7) softmax
    softmax_kernel<<<24576, 256>>>(p_sc);

    // 8) att[b] = sc[b] @ vT[b]^T      M=512 N=512 K=2048, batched 48
    hgemm<0><<<dim3(4, 4, 48), 256, GSM>>>(
        p_sc, p_vT, p_att, 2048, 512, (size_t)512 * 2048, (size_t)512 * 2048,
        (size_t)512 * 512, nullptr, nullptr);

    // 9) x = att @ woT^T + bo + emb_s  (fp32 out)
    hgemm<2><<<dim3(4, 192, 1), 256, GSM>>>(
        p_att, woT, p_x, 512, 512, 0, 0, 0, bo, p_embs);

    // 10) xn = LN(x)
    ln_kernel<<<24576, 512>>>(p_x, p_xn, lnf_g, lnf_b);

    // 11) ag = (xn @ w1Ti^T + b1) fused gelu-pair   M=24576 N=4096(il) K=512
    hgemm<3><<<dim3(32, 192, 1), 256, GSM>>>(
        p_xn, w1Ti, p_ag, 512, 2048, 0, 0, 0, b1, nullptr);

    // 12) out = ag @ w2T^T + b2 + x    M=24576 N=512 K=2048 (fp32 out)
    hgemm<2><<<dim3(4, 192, 1), 256, GSM>>>(
        p_ag, w2T, out, 2048, 512, 0, 0, 0, b2, p_x);
}

// round 6
// speedup vs baseline: 3.4843x; 1.0012x over previous
#include <cuda_runtime.h>
#include <cuda_fp16.h>
#include <math.h>
#include <stdint.h>

// ---------------------------------------------------------------------------
// B=16, T=3, N=2048, D=3, NUM_LATENTS=512, DIM=512, HIDDEN=48 (k=8), BT=48
// All GEMMs NT: C[M,N] = A[M,K] @ B[N,K]^T, fp16 in, fp32 accum,
// mma.sync.m16n8k16 + ldmatrix.x4, BK=64, 2-stage cp.async, 2 CTAs/SM.
// FFN1 GELU fused into GEMM epilogue via interleaved w1T rows.
// ---------------------------------------------------------------------------

// ------------------------- scratch (device globals) ------------------------
__device__ int    g_idx[16 * 512];
__device__ float  g_emb_s[(size_t)48 * 512 * 512];
__device__ __half g_lnq [(size_t)48 * 512 * 512];
__device__ __half g_lnc [(size_t)48 * 2048 * 512];
__device__ __half g_q   [(size_t)48 * 512 * 512];
__device__ __half g_k   [(size_t)48 * 2048 * 512];
__device__ __half g_vT  [(size_t)48 * 512 * 2048];
__device__ __half g_sc  [(size_t)48 * 512 * 2048];
__device__ __half g_att [(size_t)48 * 512 * 512];
__device__ float  g_x   [(size_t)48 * 512 * 512];
__device__ __half g_xn  [(size_t)48 * 512 * 512];
__device__ __half g_ag  [(size_t)24576 * 2048];
__device__ __half g_wc  [4194304];   // wqT|wkT|wvT|woT|w1Ti|w2T

// ------------------------- helpers -----------------------------------------
__device__ __forceinline__ void cp16(void* dst, const void* src) {
    unsigned d = (unsigned)__cvta_generic_to_shared(dst);
    asm volatile("cp.async.cg.shared.global [%0], [%1], 16;" :: "r"(d), "l"(src));
}

__device__ __forceinline__ void ldsm4(unsigned* r, uint32_t a) {
    asm volatile("ldmatrix.sync.aligned.m8n8.x4.shared.b16 {%0,%1,%2,%3}, [%4];"
                 : "=r"(r[0]), "=r"(r[1]), "=r"(r[2]), "=r"(r[3]) : "r"(a));
}

__device__ __forceinline__ void mma16(float* d, const unsigned* a, unsigned b0, unsigned b1) {
    asm volatile(
        "mma.sync.aligned.m16n8k16.row.col.f32.f16.f16.f32 "
        "{%0,%1,%2,%3}, {%4,%5,%6,%7}, {%8,%9}, {%0,%1,%2,%3};"
        : "+f"(d[0]), "+f"(d[1]), "+f"(d[2]), "+f"(d[3])
        : "r"(a[0]), "r"(a[1]), "r"(a[2]), "r"(a[3]), "r"(b0), "r"(b1));
}

__device__ __forceinline__ uint32_t smem_u32(const void* p) {
    uint32_t a;
    asm("{ .reg .u64 t; cvta.to.shared.u64 t, %1; cvt.u32.u64 %0, t; }" : "=r"(a) : "l"(p));
    return a;
}

__device__ __forceinline__ float blockReduceSum(float v, float* red) {
    #pragma unroll
    for (int o = 16; o; o >>= 1) v += __shfl_down_sync(0xffffffffu, v, o);
    int lane = threadIdx.x & 31, w = threadIdx.x >> 5;
    if (lane == 0) red[w] = v;
    __syncthreads();
    if (threadIdx.x < 32) {
        float s = (threadIdx.x < (blockDim.x >> 5)) ? red[threadIdx.x] : 0.0f;
        #pragma unroll
        for (int o = 16; o; o >>= 1) s += __shfl_down_sync(0xffffffffu, s, o);
        if (threadIdx.x == 0) red[0] = s;
    }
    __syncthreads();
    float r = red[0];
    __syncthreads();
    return r;
}

__device__ __forceinline__ float blockReduceMax(float v, float* red) {
    #pragma unroll
    for (int o = 16; o; o >>= 1) v = fmaxf(v, __shfl_down_sync(0xffffffffu, v, o));
    int lane = threadIdx.x & 31, w = threadIdx.x >> 5;
    if (lane == 0) red[w] = v;
    __syncthreads();
    if (threadIdx.x < 32) {
        float s = (threadIdx.x < (blockDim.x >> 5)) ? red[threadIdx.x] : -3.0e38f;
        #pragma unroll
        for (int o = 16; o; o >>= 1) s = fmaxf(s, __shfl_down_sync(0xffffffffu, s, o));
        if (threadIdx.x == 0) red[0] = s;
    }
    __syncthreads();
    float r = red[0];
    __syncthreads();
    return r;
}

// ------------------------- FPS ----------------------------------------------
__global__ void fps_kernel(const float* __restrict__ pc, int* __restrict__ idx) {
    int b = blockIdx.x;
    int t = threadIdx.x;
    const float* pts = pc + (size_t)b * 3 * 2048 * 3;
    int t1 = t + 1024;
    float x0 = pts[t * 3 + 0], y0 = pts[t * 3 + 1], z0 = pts[t * 3 + 2];
    float x1 = pts[t1 * 3 + 0], y1 = pts[t1 * 3 + 1], z1 = pts[t1 * 3 + 2];
    float d0 = 1e10f, d1 = 1e10f;

    __shared__ float lx, ly, lz;
    __shared__ float sv[32];
    __shared__ int   si[32];
    if (t == 0) { lx = pts[0]; ly = pts[1]; lz = pts[2]; idx[b * 512] = 0; }
    __syncthreads();

    for (int s = 1; s < 512; s++) {
        float ax = __fadd_rn(x0, -lx), ay = __fadd_rn(y0, -ly), az = __fadd_rn(z0, -lz);
        float e0 = __fadd_rn(__fadd_rn(__fmul_rn(ax, ax), __fmul_rn(ay, ay)), __fmul_rn(az, az));
        float bx = __fadd_rn(x1, -lx), by = __fadd_rn(y1, -ly), bz = __fadd_rn(z1, -lz);
        float e1 = __fadd_rn(__fadd_rn(__fmul_rn(bx, bx), __fmul_rn(by, by)), __fmul_rn(bz, bz));
        d0 = fminf(d0, e0);
        d1 = fminf(d1, e1);

        float v;
        int   vi;
        if (d1 > d0) { v = d1; vi = t1; } else { v = d0; vi = t; }
        #pragma unroll
        for (int o = 16; o; o >>= 1) {
            float ov = __shfl_down_sync(0xffffffffu, v, o);
            int   oi = __shfl_down_sync(0xffffffffu, vi, o);
            if (ov > v || (ov == v && oi < vi)) { v = ov; vi = oi; }
        }
        int lane = t & 31, w = t >> 5;
        if (lane == 0) { sv[w] = v; si[w] = vi; }
        __syncthreads();
        if (t < 32) {
            v = sv[t]; vi = si[t];
            #pragma unroll
            for (int o = 16; o; o >>= 1) {
                float ov = __shfl_down_sync(0xffffffffu, v, o);
                int   oi = __shfl_down_sync(0xffffffffu, vi, o);
                if (ov > v || (ov == v && oi < vi)) { v = ov; vi = oi; }
            }
            if (t == 0) {
                idx[b * 512 + s] = vi;
                lx = pts[vi * 3 + 0]; ly = pts[vi * 3 + 1]; lz = pts[vi * 3 + 2];
            }
        }
        __syncthreads();
    }
}

// ------------------------- fused point-embed + LayerNorm --------------------
template <bool GATHER>
__global__ void embed_ln_kernel(const float* __restrict__ pc, const float* __restrict__ pc2,
                                const float* __restrict__ basis,
                                const float* __restrict__ pe_w, const float* __restrict__ pe_b,
                                const float* __restrict__ lng, const float* __restrict__ lnb,
                                const int* __restrict__ idx,
                                float* __restrict__ emb_out, __half* __restrict__ ln_out) {
    const int j = threadIdx.x;
    const int half_ = j >> 8;
    const int col  = j & 255;
    float w[51];
    #pragma unroll
    for (int i = 0; i < 51; i++) w[i] = pe_w[i * 256 + col];
    const float pb = pe_b[col];
    const float gj = lng[j], bj = lnb[j];

    __shared__ float sx[2][3];
    __shared__ float sf[2][51];
    __shared__ float red[32];

    for (int p = 0; p < 8; p++) {
        long row = (long)blockIdx.x * 8 + p;
        long bt, n;
        if (GATHER) {
            bt = row >> 9;
            int m = (int)(row & 511);
            int b = (int)(bt / 3);
            n = idx[b * 512 + m];
        } else {
            bt = row >> 11;
            n = row & 2047;
        }
        size_t base = ((size_t)bt * 2048 + (size_t)n) * 3;
        if (j < 3)           sx[0][j]     = pc[base + j];
        else if (j < 6)      sx[1][j - 3] = pc2[base + j - 3];
        __syncthreads();

        if (j < 24) {
            float pr = sx[0][0] * basis[j] + sx[0][1] * basis[24 + j] + sx[0][2] * basis[48 + j];
            sf[0][j] = sinf(pr);
            sf[0][24 + j] = cosf(pr);
        } else if (j >= 32 && j < 56) {
            int e = j - 32;
            float pr = sx[1][0] * basis[e] + sx[1][1] * basis[24 + e] + sx[1][2] * basis[48 + e];
            sf[1][e] = sinf(pr);
            sf[1][24 + e] = cosf(pr);
        } else if (j >= 64 && j < 67) {
            sf[0][48 + (j - 64)] = sx[0][j - 64];
        } else if (j >= 67 && j < 70) {
            sf[1][48 + (j - 67)] = sx[1][j - 67];
        }
        __syncthreads();

        float acc = pb;
        #pragma unroll
        for (int i = 0; i < 51; i++) acc += w[i] * sf[half_][i];

        float mean = blockReduceSum(acc, red) * (1.0f / 512.0f);
        float d = acc - mean;
        float var = blockReduceSum(d * d, red) * (1.0f / 512.0f);
        float ln = d * rsqrtf(var + 1e-5f) * gj + bj;

        size_t o = (size_t)row * 512 + j;
        if (GATHER) emb_out[o] = acc;
        ln_out[o] = __float2half_rn(ln);
        __syncthreads();
    }
}

// ------------------------- fp16 tensor-core NT GEMM (v3) --------------------
// BM=BN=128, BK=64 halves, 256 threads, 8 warps (2m x 4n), warp 64x32.
// ldmatrix.x4, 2-stage cp.async, 2 CTAs/SM.
// EPI: 0 none(half out), 2 +bias+res -> fp32 out, 3 gelu-pair -> half out.
#define ASTR 72                       // smem row stride (halves)
#define TSZ  (128 * ASTR)             // halves per tile per stage
#define TSB  (TSZ * 2)                // bytes per tile per stage
#define GSM  (4 * TSB)                // 2 stages x (A + B) = 73728 B

template <int EPI>
__global__ void __launch_bounds__(256, 2)
hgemm(const __half* __restrict__ A, const __half* __restrict__ B, void* __restrict__ Cv,
      int K, int ldc, size_t sA, size_t sB, size_t sC,
      const float* __restrict__ bias, const float* __restrict__ res) {
    extern __shared__ __half sm[];
    __half* Asm = sm;            // 2 stages
    __half* Bsm = sm + 2 * TSZ;  // 2 stages

    const int t = threadIdx.x;
    const int lane = t & 31, wid = t >> 5;
    const size_t bm = (size_t)blockIdx.y * 128, bn = (size_t)blockIdx.x * 128;
    A += (size_t)blockIdx.z * sA + bm * (size_t)K;
    B += (size_t)blockIdx.z * sB + bn * (size_t)K;
    const float* resp = (EPI == 2) ? res + (size_t)blockIdx.z * sC : nullptr;

    const int wm = (wid >> 2) * 64, wn = (wid & 3) * 32;
    const int g = lane >> 2, tg = lane & 3;

    float acc[4][4][4];
    #pragma unroll
    for (int mi = 0; mi < 4; mi++)
        #pragma unroll
        for (int ni = 0; ni < 4; ni++)
            #pragma unroll
            for (int r = 0; r < 4; r++) acc[mi][ni][r] = 0.0f;

    const int T = K >> 6;

    auto issue = [&](int kt) {
        const int s = kt & 1;
        const __half* Ag = A + kt * 64;
        const __half* Bg = B + kt * 64;
        __half* Ab = Asm + s * TSZ;
        __half* Bb = Bsm + s * TSZ;
        #pragma unroll
        for (int i = 0; i < 4; i++) {
            int seg = t + 256 * i;
            int row = seg >> 3, ho = (seg & 7) * 8;
            cp16(Ab + row * ASTR + ho, Ag + (size_t)row * K + ho);
            cp16(Bb + row * ASTR + ho, Bg + (size_t)row * K + ho);
        }
        asm volatile("cp.async.commit_group;");
    };

    const int lr16 = lane & 15, lc8 = (lane >> 4) * 8;
    const uint32_t aU = smem_u32(Asm) + (uint32_t)(((wm + lr16) * ASTR + lc8) * 2);
    const uint32_t bU = smem_u32(Bsm) + (uint32_t)(((wn + lr16) * ASTR + lc8) * 2);

    issue(0);
    for (int kt = 0; kt < T; kt++) {
        if (kt + 1 < T) issue(kt + 1);
        else asm volatile("cp.async.commit_group;");
        asm volatile("cp.async.wait_group 1;");
        __syncthreads();

        const uint32_t as = aU + (uint32_t)((kt & 1) * TSB);
        const uint32_t bs = bU + (uint32_t)((kt & 1) * TSB);

        #pragma unroll
        for (int ks = 0; ks < 4; ks++) {
            unsigned af[4][4], bf[2][4];
            #pragma unroll
            for (int mi = 0; mi < 4; mi++)
                ldsm4(af[mi], as + (uint32_t)((mi * 16 * ASTR + ks * 16) * 2));
            #pragma unroll
            for (int p = 0; p < 2; p++)
                ldsm4(bf[p], bs + (uint32_t)((p * 16 * ASTR + ks * 16) * 2));
            #pragma unroll
            for (int mi = 0; mi < 4; mi++) {
                #pragma unroll
                for (int p = 0; p < 2; p++) {
                    mma16(acc[mi][2 * p + 0], af[mi], bf[p][0], bf[p][2]);
                    mma16(acc[mi][2 * p + 1], af[mi], bf[p][1], bf[p][3]);
                }
            }
        }
        __syncthreads();
    }

    // ---- epilogue ----
    float*  Cf = (float*)Cv + ((EPI == 2) ? (size_t)blockIdx.z * sC : 0);
    __half* Ch = (__half*)Cv + ((EPI != 2) ? (size_t)blockIdx.z * sC : 0);

    #pragma unroll
    for (int mi = 0; mi < 4; mi++) {
        size_t r = bm + wm + mi * 16 + g;
        #pragma unroll
        for (int ni = 0; ni < 4; ni++) {
            size_t c = bn + wn + ni * 8 + tg * 2;
            float v0 = acc[mi][ni][0], v1 = acc[mi][ni][1];
            float v2 = acc[mi][ni][2], v3 = acc[mi][ni][3];
            if (EPI == 2) {
                float b0 = bias[c], b1 = bias[c + 1];
                float2 r0v = *(const float2*)(resp + r * ldc + c);
                float2 r1v = *(const float2*)(resp + (r + 8) * ldc + c);
                *(float2*)(Cf + r * ldc + c) = make_float2(v0 + b0 + r0v.x, v1 + b1 + r0v.y);
                *(float2*)(Cf + (r + 8) * ldc + c) = make_float2(v2 + b0 + r1v.x, v3 + b1 + r1v.y);
            } else if (EPI == 3) {
                size_t j = c >> 1;
                float ba = bias[j], bg = bias[j + 2048];
                float a0 = v0 + ba, g0 = v1 + bg;
                float a1 = v2 + ba, g1 = v3 + bg;
                float ge0 = 0.5f * g0 * (1.0f + erff(g0 * 0.7071067811865475f));
                float ge1 = 0.5f * g1 * (1.0f + erff(g1 * 0.7071067811865475f));
                Ch[r * ldc + j] = __float2half_rn(a0 * ge0);
                Ch[(r + 8) * ldc + j] = __float2half_rn(a1 * ge1);
            } else {
                *(__half2*)(Ch + r * ldc + c) = __floats2half2_rn(v0, v1);
                *(__half2*)(Ch + (r + 8) * ldc + c) = __floats2half2_rn(v2, v3);
            }
        }
    }
}

// ------------------------- softmax (rows of 2048, half) ----------------------
__global__ void softmax_kernel(__half* __restrict__ s) {
    const size_t row = blockIdx.x;
    __half* p = s + row * 2048;
    const int t = threadIdx.x;
    const float scale = 0.044194173824159216f;
    __shared__ float red[32];
    float v[8];
    float mx = -3.0e38f;
    #pragma unroll
    for (int i = 0; i < 8; i++) {
        v[i] = __half2float(p[t + i * 256]) * scale;
        mx = fmaxf(mx, v[i]);
    }
    mx = blockReduceMax(mx, red);
    float sum = 0.0f;
    #pragma unroll
    for (int i = 0; i < 8; i++) {
        v[i] = expf(v[i] - mx);
        sum += v[i];
    }
    sum = blockReduceSum(sum, red);
    float inv = 1.0f / sum;
    #pragma unroll
    for (int i = 0; i < 8; i++) p[t + i * 256] = __float2half_rn(v[i] * inv);
}

// ------------------------- LayerNorm (512), fp32 in, half out ---------------
__global__ void ln_kernel(const float* __restrict__ x, __half* __restrict__ y,
                          const float* __restrict__ g, const float* __restrict__ b) {
    const size_t row = blockIdx.x;
    const int j = threadIdx.x;
    __shared__ float red[32];
    float v = x[row * 512 + j];
    float mean = blockReduceSum(v, red) * (1.0f / 512.0f);
    float d = v - mean;
    float var = blockReduceSum(d * d, red) * (1.0f / 512.0f);
    y[row * 512 + j] = __float2half_rn(d * rsqrtf(var + 1e-5f) * g[j] + b[j]);
}

// ------------------------- transpose fp32 -> fp16 (optional interleave) -----
__global__ void transcvt_kernel(const float* __restrict__ src, __half* __restrict__ dst,
                                int R, int ld, int coff, int inter) {
    __shared__ float tile[32][33];
    int c0 = blockIdx.x * 32, r0 = blockIdx.y * 32;
    int tx = threadIdx.x & 31, ty = threadIdx.x >> 5;
    #pragma unroll
    for (int i = 0; i < 32; i += 8)
        tile[ty + i][tx] = src[(size_t)(r0 + ty + i) * ld + coff + c0 + tx];
    __syncthreads();
    #pragma unroll
    for (int i = 0; i < 32; i += 8) {
        int c = c0 + ty + i;
        int dr = inter ? ((c < inter) ? 2 * c : 2 * (c - inter) + 1) : c;
        dst[(size_t)dr * R + r0 + tx] = __float2half_rn(tile[tx][ty + i]);
    }
}

// ---------------------------------------------------------------------------
extern "C" void kernel_launch(void* const* d_in, const int* in_sizes, int n_in,
                              void* d_out, int out_size) {
    const float* pc    = (const float*)d_in[0];
    const float* pc2   = (const float*)d_in[1];
    const float* basis = (const float*)d_in[2];
    const float* pe_w  = (const float*)d_in[3];
    const float* pe_b  = (const float*)d_in[4];
    const float* lnq_g = (const float*)d_in[5];
    const float* lnq_b = (const float*)d_in[6];
    const float* lnc_g = (const float*)d_in[7];
    const float* lnc_b = (const float*)d_in[8];
    const float* wq    = (const float*)d_in[9];
    const float* wkv   = (const float*)d_in[10];
    const float* wo    = (const float*)d_in[11];
    const float* bo    = (const float*)d_in[12];
    const float* lnf_g = (const float*)d_in[13];
    const float* lnf_b = (const float*)d_in[14];
    const float* w1    = (const float*)d_in[15];
    const float* b1    = (const float*)d_in[16];
    const float* w2    = (const float*)d_in[17];
    const float* b2    = (const float*)d_in[18];
    float* out = (float*)d_out;

    void *vp;
    int*    p_idx;  cudaGetSymbolAddress(&vp, g_idx);   p_idx  = (int*)vp;
    float*  p_embs; cudaGetSymbolAddress(&vp, g_emb_s); p_embs = (float*)vp;
    __half* p_lnq;  cudaGetSymbolAddress(&vp, g_lnq);   p_lnq  = (__half*)vp;
    __half* p_lnc;  cudaGetSymbolAddress(&vp, g_lnc);   p_lnc  = (__half*)vp;
    __half* p_q;    cudaGetSymbolAddress(&vp, g_q);     p_q    = (__half*)vp;
    __half* p_k;    cudaGetSymbolAddress(&vp, g_k);     p_k    = (__half*)vp;
    __half* p_vT;   cudaGetSymbolAddress(&vp, g_vT);    p_vT   = (__half*)vp;
    __half* p_sc;   cudaGetSymbolAddress(&vp, g_sc);    p_sc   = (__half*)vp;
    __half* p_att;  cudaGetSymbolAddress(&vp, g_att);   p_att  = (__half*)vp;
    float*  p_x;    cudaGetSymbolAddress(&vp, g_x);     p_x    = (float*)vp;
    __half* p_xn;   cudaGetSymbolAddress(&vp, g_xn);    p_xn   = (__half*)vp;
    __half* p_ag;   cudaGetSymbolAddress(&vp, g_ag);    p_ag   = (__half*)vp;
    __half* p_wc;   cudaGetSymbolAddress(&vp, g_wc);    p_wc   = (__half*)vp;

    __half* wqT  = p_wc;                 // [512,512]
    __half* wkT  = p_wc + 262144;        // [512,512]
    __half* wvT  = p_wc + 524288;        // [512,512]
    __half* woT  = p_wc + 786432;        // [512,512]
    __half* w1Ti = p_wc + 1048576;       // [4096,512] interleaved a/g
    __half* w2T  = p_wc + 3145728;       // [512,2048]

    cudaFuncSetAttribute(hgemm<0>, cudaFuncAttributeMaxDynamicSharedMemorySize, GSM);
    cudaFuncSetAttribute(hgemm<2>, cudaFuncAttributeMaxDynamicSharedMemorySize, GSM);
    cudaFuncSetAttribute(hgemm<3>, cudaFuncAttributeMaxDynamicSharedMemorySize, GSM);

    // 0) weight transpose + fp16 convert (w1 interleaved a/g)
    transcvt_kernel<<<dim3(16, 16), 256>>>(wq,  wqT, 512, 512, 0, 0);
    transcvt_kernel<<<dim3(16, 16), 256>>>(wkv, wkT, 512, 1024, 0, 0);
    transcvt_kernel<<<dim3(16, 16), 256>>>(wkv, wvT, 512, 1024, 512, 0);
    transcvt_kernel<<<dim3(16, 16), 256>>>(wo,  woT, 512, 512, 0, 0);
    transcvt_kernel<<<dim3(128, 16), 256>>>(w1, w1Ti, 512, 4096, 0, 2048);
    transcvt_kernel<<<dim3(16, 64), 256>>>(w2, w2T, 2048, 512, 0, 0);

    // 1) FPS
    fps_kernel<<<16, 1024>>>(pc, p_idx);

    // 2) fused embed + LN
    embed_ln_kernel<true ><<<48 * 512 / 8, 512>>>(pc, pc2, basis, pe_w, pe_b,
                                                  lnq_g, lnq_b, p_idx, p_embs, p_lnq);
    embed_ln_kernel<false><<<48 * 2048 / 8, 512>>>(pc, pc2, basis, pe_w, pe_b,
                                                   lnc_g, lnc_b, nullptr, nullptr, p_lnc);

    // 3) q = lnq @ wqT^T               M=24576 N=512 K=512
    hgemm<0><<<dim3(4, 192, 1), 256, GSM>>>(
        p_lnq, wqT, p_q, 512, 512, 0, 0, 0, nullptr, nullptr);

    // 4) k = lnc @ wkT^T               M=98304 N=512 K=512
    hgemm<0><<<dim3(4, 768, 1), 256, GSM>>>(
        p_lnc, wkT, p_k, 512, 512, 0, 0, 0, nullptr, nullptr);

    // 5) vT[b] = wvT @ lnc[b]^T        M=512 N=2048 K=512, batched 48
    hgemm<0><<<dim3(16, 4, 48), 256, GSM>>>(
        wvT, p_lnc, p_vT, 512, 2048, 0, (size_t)2048 * 512, (size_t)512 * 2048,
        nullptr, nullptr);

    // 6) sc[b] = q[b] @ k[b]^T         M=512 N=2048 K=512, batched 48
    hgemm<0><<<dim3(16, 4, 48), 256, GSM>>>(
        p_q, p_k, p_sc, 512, 2048, (size_t)512 * 512, (size_t)2048 * 512,
        (size_t)512 * 2048, nullptr, nullptr);

    // 7) softmax
    softmax_kernel<<<24576, 256>>>(p_sc);

    // 8) att[b] = sc[b] @ vT[b]^T      M=512 N=512 K=2048, batched 48
    hgemm<0><<<dim3(4, 4, 48), 256, GSM>>>(
        p_sc, p_vT, p_att, 2048, 512, (size_t)512 * 2048, (size_t)512 * 2048,
        (size_t)512 * 512, nullptr, nullptr);

    // 9) x = att @ woT^T + bo + emb_s  (fp32 out)
    hgemm<2><<<dim3(4, 192, 1), 256, GSM>>>(
        p_att, woT, p_x, 512, 512, 0, 0, 0, bo, p_embs);

    // 10) xn = LN(x)
    ln_kernel<<<24576, 512>>>(p_x, p_xn, lnf_g, lnf_b);

    // 11) ag = (xn @ w1Ti^T + b1) fused gelu-pair   M=24576 N=4096(il) K=512
    hgemm<3><<<dim3(32, 192, 1), 256, GSM>>>(
        p_xn, w1Ti, p_ag, 512, 2048, 0, 0, 0, b1, nullptr);

    // 12) out = ag @ w2T^T + b2 + x    M=24576 N=512 K=2048 (fp32 out)
    hgemm<2><<<dim3(4, 192, 1), 256, GSM>>>(
        p_ag, w2T, out, 2048, 512, 0, 0, 0, b2, p_x);
}